// round 3
// baseline (speedup 1.0000x reference)
#include <cuda_runtime.h>
#include <cstdint>

typedef unsigned long long ull;

struct P12 { const float* W[4]; const float* B[4]; const float* R[4]; };

// persistent scratch (no allocations allowed)
__device__ float g_X[(size_t)512 * 256 * 1024];   // pre-activations [t][b][g*256+u]
__device__ float g_h[2][256 * 256];               // ping-pong h
__device__ unsigned g_cnt[8];                     // per-batch-group barrier counters
__device__ volatile unsigned g_gen[8];            // per-group generation (monotonic across replays)

__device__ __forceinline__ ull pk(float x, float y) {
    ull r; asm("mov.b64 %0, {%1,%2};" : "=l"(r) : "f"(x), "f"(y)); return r;
}
__device__ __forceinline__ void fma2(ull& d, ull a, ull b) {
    asm("fma.rn.f32x2 %0, %1, %2, %0;" : "+l"(d) : "l"(a), "l"(b));
}
__device__ __forceinline__ float lane_sum(ull v) {
    float x, y; asm("mov.b64 {%0,%1}, %2;" : "=f"(x), "=f"(y) : "l"(v)); return x + y;
}
__device__ __forceinline__ float sigm(float x) { return 1.f / (1.f + __expf(-x)); }

// ---------------------------------------------------------------------------
// Kernel 1: X[m][n] = A[m][:512] @ W_g[u][:512]^T + (b_g[u] + r_g[u])
//   m = t*256+b (131072 rows), n = g*256+u (1024 cols)
//   CTA tile 128x128, K-block 16, per-thread 8x8 via f32x2 k-pair packing.
// ---------------------------------------------------------------------------
__global__ void __launch_bounds__(256, 1) g1_kernel(const float* __restrict__ A, P12 p) {
    __shared__ ull sA[8 * 128];   // [k2][m] packed (k even, k odd)
    __shared__ ull sB[8 * 128];   // [k2][n]
    const int tid = threadIdx.x, tn = tid & 15, tm = tid >> 4;  // 16x16 threads
    const int n0 = blockIdx.x * 128;
    const int m0 = blockIdx.y * 128;
    const int gate = n0 >> 8, ubase = n0 & 255;
    const float* __restrict__ Wg = p.W[gate];

    ull acc[8][8];
#pragma unroll
    for (int i = 0; i < 8; i++) {
#pragma unroll
        for (int j = 0; j < 8; j++) acc[i][j] = 0ull;
    }

    for (int kb = 0; kb < 512; kb += 16) {
#pragma unroll
        for (int i = 0; i < 2; i++) {
            int fidx = tid + 256 * i;
            int row = fidx >> 2, q = fidx & 3;
            float4 va = *(const float4*)(A + (size_t)(m0 + row) * 512 + kb + q * 4);
            sA[(q * 2) * 128 + row]     = pk(va.x, va.y);
            sA[(q * 2 + 1) * 128 + row] = pk(va.z, va.w);
            float4 vb = *(const float4*)(Wg + (size_t)(ubase + row) * 768 + kb + q * 4);
            sB[(q * 2) * 128 + row]     = pk(vb.x, vb.y);
            sB[(q * 2 + 1) * 128 + row] = pk(vb.z, vb.w);
        }
        __syncthreads();
#pragma unroll
        for (int k2 = 0; k2 < 8; k2++) {
            ull a[8], w[8];
#pragma unroll
            for (int i = 0; i < 8; i++) a[i] = sA[k2 * 128 + tm + 16 * i];
#pragma unroll
            for (int j = 0; j < 8; j++) w[j] = sB[k2 * 128 + tn + 16 * j];
#pragma unroll
            for (int i = 0; i < 8; i++) {
#pragma unroll
                for (int j = 0; j < 8; j++) fma2(acc[i][j], a[i], w[j]);
            }
        }
        __syncthreads();
    }

#pragma unroll
    for (int j = 0; j < 8; j++) {
        int ui = ubase + tn + 16 * j;
        float bv = p.B[gate][ui] + p.R[gate][ui];
#pragma unroll
        for (int i = 0; i < 8; i++) {
            int m = m0 + tm + 16 * i;
            g_X[(size_t)m * 1024 + n0 + tn + 16 * j] = lane_sum(acc[i][j]) + bv;
        }
    }
}

// ---------------------------------------------------------------------------
// Kernel 2: persistent recurrence. Grid (16 unit-tiles, 8 batch-groups),
// 128 threads. Each CTA: units u0..u0+15 (all 4 gates, c in regs),
// batches b0..b0+31. Wh slice resident in SMEM; per-group barrier per step.
// ---------------------------------------------------------------------------
__global__ void __launch_bounds__(128, 1) rnn_kernel(P12 p, float* __restrict__ out,
                                                     int out_elems) {
    extern __shared__ ull sh[];
    ull* WS = sh;           // [128 k2][64 r]  (r = gate*16 + ui) packed k-pairs
    ull* HS = sh + 8192;    // [32 b][129]     padded (bank-conflict-free)

    const int tid = threadIdx.x, tn = tid & 15, tm = tid >> 4;  // tm 0..7
    const int u0 = blockIdx.x * 16, bb = blockIdx.y, b0 = bb * 32;
    const int unit = u0 + tn;

    // load Wh slice once (reused 512 steps)
    for (int idx = tid; idx < 8192; idx += 128) {
        int r = idx & 63, k2 = idx >> 6;
        int g = r >> 4, ui = r & 15;
        const float* wp = p.W[g] + (size_t)(u0 + ui) * 768 + 512 + 2 * k2;
        WS[k2 * 64 + r] = pk(wp[0], wp[1]);
    }
    __shared__ unsigned s_gen0;
    if (tid == 0) s_gen0 = g_gen[bb];
    __syncthreads();
    const unsigned gen0 = s_gen0;

    float c[4] = {0.f, 0.f, 0.f, 0.f};

    for (int t = 0; t < 512; t++) {
        ull acc[4][4];  // [batch i][gate j], lanes = even/odd k partials
        const float* Xt = g_X + (size_t)t * 256 * 1024;
#pragma unroll
        for (int i = 0; i < 4; i++) {
            int b = b0 + tm + 8 * i;
#pragma unroll
            for (int j = 0; j < 4; j++)
                acc[i][j] = (ull)__float_as_uint(Xt[(size_t)b * 1024 + j * 256 + unit]);
        }

        if (t > 0) {
            const float4* hsrc = (const float4*)g_h[(t + 1) & 1];  // == (t-1)&1
#pragma unroll
            for (int i = 0; i < 16; i++) {
                int idx = tid + 128 * i;
                int bi = idx >> 6, q = idx & 63;
                float4 v = __ldcg(hsrc + (size_t)(b0 + bi) * 64 + q);
                HS[bi * 129 + 2 * q]     = pk(v.x, v.y);
                HS[bi * 129 + 2 * q + 1] = pk(v.z, v.w);
            }
            __syncthreads();
#pragma unroll 8
            for (int k2 = 0; k2 < 128; k2++) {
                ull a[4], w[4];
#pragma unroll
                for (int i = 0; i < 4; i++) a[i] = HS[(tm + 8 * i) * 129 + k2];
#pragma unroll
                for (int j = 0; j < 4; j++) w[j] = WS[k2 * 64 + tn + 16 * j];
#pragma unroll
                for (int i = 0; i < 4; i++) {
#pragma unroll
                    for (int j = 0; j < 4; j++) fma2(acc[i][j], a[i], w[j]);
                }
            }
        }

        float* hdst = g_h[t & 1];
#pragma unroll
        for (int i = 0; i < 4; i++) {
            float pf = sigm(lane_sum(acc[i][0]));
            float pi = sigm(lane_sum(acc[i][1]));
            float pu = sigm(lane_sum(acc[i][2]));
            float po = sigm(lane_sum(acc[i][3]));
            c[i] = pf * c[i] + pi * pu;
            float h = po * tanhf(c[i]);
            int b = b0 + tm + 8 * i;
            out[(size_t)t * 65536 + b * 256 + unit] = h;
            hdst[b * 256 + unit] = h;
            if (t == 511 && out_elems >= 33685504) {
                out[33554432 + b * 256 + unit] = h;      // hx
                out[33619968 + b * 256 + unit] = c[i];   // cx
            }
        }

        if (t < 511) {
            __threadfence();
            __syncthreads();
            if (tid == 0) {
                unsigned want = gen0 + (unsigned)t + 1u;
                unsigned a = atomicAdd(&g_cnt[bb], 1u);
                if (a == 15u) {
                    g_cnt[bb] = 0u;
                    __threadfence();
                    g_gen[bb] = want;
                } else {
                    while ((int)(g_gen[bb] - want) < 0) { }
                }
            }
            __syncthreads();
        }
    }
}

// ---------------------------------------------------------------------------
extern "C" void kernel_launch(void* const* d_in, const int* in_sizes, int n_in,
                              void* d_out, int out_size) {
    const float* x = (const float*)d_in[0];
    P12 p;
    if (n_in >= 13 && in_sizes[3] == 196608) {
        // signature order: W f,b f, W i,b i, ... then rf,ri,ru,ro
        for (int g = 0; g < 4; g++) {
            p.W[g] = (const float*)d_in[1 + 2 * g];
            p.B[g] = (const float*)d_in[2 + 2 * g];
            p.R[g] = (const float*)d_in[9 + g];
        }
    } else {
        // dict order: (W,b,r) per gate
        for (int g = 0; g < 4; g++) {
            p.W[g] = (const float*)d_in[1 + 3 * g];
            p.B[g] = (const float*)d_in[2 + 3 * g];
            p.R[g] = (const float*)d_in[3 + 3 * g];
        }
    }

    g1_kernel<<<dim3(8, 1024), 256>>>(x, p);

    cudaFuncSetAttribute(rnn_kernel, cudaFuncAttributeMaxDynamicSharedMemorySize, 102400);
    rnn_kernel<<<dim3(16, 8), 128, 98560>>>(p, (float*)d_out, out_size);
}

// round 4
// speedup vs baseline: 1.0992x; 1.0992x over previous
#include <cuda_runtime.h>
#include <cstdint>

typedef unsigned long long ull;

struct P12 { const float* W[4]; const float* B[4]; const float* R[4]; };

// persistent scratch (no allocations allowed)
__device__ float g_X[(size_t)512 * 256 * 1024];   // pre-activations [t][b][g*256+u]
__device__ float g_h[2][256 * 256];               // ping-pong h
__device__ unsigned g_cnt[8];                     // per-batch-group barrier counters
__device__ volatile unsigned g_gen[8];            // per-group generation (monotonic)

__device__ __forceinline__ ull pk(float x, float y) {
    ull r; asm("mov.b64 %0, {%1,%2};" : "=l"(r) : "f"(x), "f"(y)); return r;
}
__device__ __forceinline__ void fma2(ull& d, ull a, ull b) {
    asm("fma.rn.f32x2 %0, %1, %2, %0;" : "+l"(d) : "l"(a), "l"(b));
}
__device__ __forceinline__ float lane_sum(ull v) {
    float x, y; asm("mov.b64 {%0,%1}, %2;" : "=f"(x), "=f"(y) : "l"(v)); return x + y;
}
__device__ __forceinline__ float sigm(float x) { return 1.f / (1.f + __expf(-x)); }

// ---------------------------------------------------------------------------
// Kernel 1: X[m][n] = A[m][:512] @ W_g[u][:512]^T + (b_g[u] + r_g[u])
//   m = t*256+b (131072 rows), n = g*256+u (1024 cols)
//   CTA tile 128x128, K-block 16, 8x8/thread via f32x2; register-staged
//   double-buffered SMEM (LDG next block during compute of current).
// ---------------------------------------------------------------------------
__global__ void __launch_bounds__(256, 1) g1_kernel(const float* __restrict__ A, P12 p) {
    __shared__ ull sA[2][8 * 128];   // [stage][k2][m] packed (k even, k odd)
    __shared__ ull sB[2][8 * 128];   // [stage][k2][n]
    const int tid = threadIdx.x, tn = tid & 15, tm = tid >> 4;
    const int n0 = blockIdx.x * 128;
    const int m0 = blockIdx.y * 128;
    const int gate = n0 >> 8, ubase = n0 & 255;
    const float* __restrict__ Wg = p.W[gate];

    // per-thread load slots: fidx = tid + 256*i -> row = fidx>>2, q = fidx&3
    const int row0 = tid >> 2, q0 = tid & 3;
    const int row1 = (tid + 256) >> 2, q1 = tid & 3;  // fidx&3 == tid&3

    ull acc[8][8];
#pragma unroll
    for (int i = 0; i < 8; i++)
#pragma unroll
        for (int j = 0; j < 8; j++) acc[i][j] = 0ull;

    float4 va0, va1, vb0, vb1;
    // prologue: load kb=0, stage 0
    va0 = *(const float4*)(A + (size_t)(m0 + row0) * 512 + q0 * 4);
    va1 = *(const float4*)(A + (size_t)(m0 + row1) * 512 + q1 * 4);
    vb0 = *(const float4*)(Wg + (size_t)(ubase + row0) * 768 + q0 * 4);
    vb1 = *(const float4*)(Wg + (size_t)(ubase + row1) * 768 + q1 * 4);
    sA[0][(q0 * 2) * 128 + row0] = pk(va0.x, va0.y);
    sA[0][(q0 * 2 + 1) * 128 + row0] = pk(va0.z, va0.w);
    sA[0][(q1 * 2) * 128 + row1] = pk(va1.x, va1.y);
    sA[0][(q1 * 2 + 1) * 128 + row1] = pk(va1.z, va1.w);
    sB[0][(q0 * 2) * 128 + row0] = pk(vb0.x, vb0.y);
    sB[0][(q0 * 2 + 1) * 128 + row0] = pk(vb0.z, vb0.w);
    sB[0][(q1 * 2) * 128 + row1] = pk(vb1.x, vb1.y);
    sB[0][(q1 * 2 + 1) * 128 + row1] = pk(vb1.z, vb1.w);
    __syncthreads();

    for (int kb = 0; kb < 32; kb++) {
        const int st = kb & 1;
        if (kb < 31) {  // prefetch next K-block into registers
            int k = (kb + 1) * 16;
            va0 = *(const float4*)(A + (size_t)(m0 + row0) * 512 + k + q0 * 4);
            va1 = *(const float4*)(A + (size_t)(m0 + row1) * 512 + k + q1 * 4);
            vb0 = *(const float4*)(Wg + (size_t)(ubase + row0) * 768 + k + q0 * 4);
            vb1 = *(const float4*)(Wg + (size_t)(ubase + row1) * 768 + k + q1 * 4);
        }
#pragma unroll
        for (int k2 = 0; k2 < 8; k2++) {
            ull a[8], w[8];
#pragma unroll
            for (int i = 0; i < 8; i++) a[i] = sA[st][k2 * 128 + tm + 16 * i];
#pragma unroll
            for (int j = 0; j < 8; j++) w[j] = sB[st][k2 * 128 + tn + 16 * j];
#pragma unroll
            for (int i = 0; i < 8; i++)
#pragma unroll
                for (int j = 0; j < 8; j++) fma2(acc[i][j], a[i], w[j]);
        }
        __syncthreads();
        if (kb < 31) {
            const int ns = st ^ 1;
            sA[ns][(q0 * 2) * 128 + row0] = pk(va0.x, va0.y);
            sA[ns][(q0 * 2 + 1) * 128 + row0] = pk(va0.z, va0.w);
            sA[ns][(q1 * 2) * 128 + row1] = pk(va1.x, va1.y);
            sA[ns][(q1 * 2 + 1) * 128 + row1] = pk(va1.z, va1.w);
            sB[ns][(q0 * 2) * 128 + row0] = pk(vb0.x, vb0.y);
            sB[ns][(q0 * 2 + 1) * 128 + row0] = pk(vb0.z, vb0.w);
            sB[ns][(q1 * 2) * 128 + row1] = pk(vb1.x, vb1.y);
            sB[ns][(q1 * 2 + 1) * 128 + row1] = pk(vb1.z, vb1.w);
            __syncthreads();
        }
    }

#pragma unroll
    for (int j = 0; j < 8; j++) {
        int ui = ubase + tn + 16 * j;
        float bv = p.B[gate][ui] + p.R[gate][ui];
#pragma unroll
        for (int i = 0; i < 8; i++) {
            int m = m0 + tm + 16 * i;
            g_X[(size_t)m * 1024 + n0 + tn + 16 * j] = lane_sum(acc[i][j]) + bv;
        }
    }
}

// ---------------------------------------------------------------------------
// Kernel 2: persistent recurrence. Grid (16 unit-tiles, 8 batch-groups),
// 256 threads (2 warps/SMSP). CTA: units u0..u0+15 (all 4 gates, c in regs),
// batches b0..b0+31 (2 per thread). Wh slice resident in SMEM; per-group
// barrier per step.
// ---------------------------------------------------------------------------
__global__ void __launch_bounds__(256, 1) rnn_kernel(P12 p, float* __restrict__ out,
                                                     int out_elems) {
    extern __shared__ ull sh[];
    ull* WS = sh;           // [128 k2][64 r]  (r = gate*16 + ui) packed k-pairs
    ull* HS = sh + 8192;    // [32 b][129]     padded

    const int tid = threadIdx.x, tn = tid & 15, tm = tid >> 4;  // tm 0..15
    const int u0 = blockIdx.x * 16, bb = blockIdx.y, b0 = bb * 32;
    const int unit = u0 + tn;

    // load Wh slice once (reused 512 steps)
    for (int idx = tid; idx < 8192; idx += 256) {
        int r = idx & 63, k2 = idx >> 6;
        int g = r >> 4, ui = r & 15;
        const float* wp = p.W[g] + (size_t)(u0 + ui) * 768 + 512 + 2 * k2;
        WS[k2 * 64 + r] = pk(wp[0], wp[1]);
    }
    __shared__ unsigned s_gen0;
    if (tid == 0) s_gen0 = g_gen[bb];
    __syncthreads();
    const unsigned gen0 = s_gen0;

    float c[2] = {0.f, 0.f};

    for (int t = 0; t < 512; t++) {
        ull acc[2][4];  // [batch i][gate j], lanes = even/odd k partials
        const float* Xt = g_X + (size_t)t * 256 * 1024;
#pragma unroll
        for (int i = 0; i < 2; i++) {
            int b = b0 + tm + 16 * i;
#pragma unroll
            for (int j = 0; j < 4; j++)
                acc[i][j] = (ull)__float_as_uint(Xt[(size_t)b * 1024 + j * 256 + unit]);
        }

        if (t > 0) {
            const float4* hsrc = (const float4*)g_h[(t + 1) & 1];  // == (t-1)&1
#pragma unroll
            for (int i = 0; i < 8; i++) {
                int idx = tid + 256 * i;
                int bi = idx >> 6, q = idx & 63;
                float4 v = __ldcg(hsrc + (size_t)(b0 + bi) * 64 + q);
                HS[bi * 129 + 2 * q] = pk(v.x, v.y);
                HS[bi * 129 + 2 * q + 1] = pk(v.z, v.w);
            }
            __syncthreads();
#pragma unroll 8
            for (int k2 = 0; k2 < 128; k2++) {
                ull a[2], w[4];
#pragma unroll
                for (int i = 0; i < 2; i++) a[i] = HS[(tm + 16 * i) * 129 + k2];
#pragma unroll
                for (int j = 0; j < 4; j++) w[j] = WS[k2 * 64 + tn + 16 * j];
#pragma unroll
                for (int i = 0; i < 2; i++)
#pragma unroll
                    for (int j = 0; j < 4; j++) fma2(acc[i][j], a[i], w[j]);
            }
        }

        float* hdst = g_h[t & 1];
#pragma unroll
        for (int i = 0; i < 2; i++) {
            float pf = sigm(lane_sum(acc[i][0]));
            float pi = sigm(lane_sum(acc[i][1]));
            float pu = sigm(lane_sum(acc[i][2]));
            float po = sigm(lane_sum(acc[i][3]));
            c[i] = pf * c[i] + pi * pu;
            float h = po * tanhf(c[i]);
            int b = b0 + tm + 16 * i;
            out[(size_t)t * 65536 + b * 256 + unit] = h;
            hdst[b * 256 + unit] = h;
            if (t == 511 && out_elems >= 33685504) {
                out[33554432 + b * 256 + unit] = h;      // hx
                out[33619968 + b * 256 + unit] = c[i];   // cx
            }
        }

        if (t < 511) {
            __threadfence();
            __syncthreads();
            if (tid == 0) {
                unsigned want = gen0 + (unsigned)t + 1u;
                unsigned a = atomicAdd(&g_cnt[bb], 1u);
                if (a == 15u) {
                    g_cnt[bb] = 0u;
                    __threadfence();
                    g_gen[bb] = want;
                } else {
                    while ((int)(g_gen[bb] - want) < 0) { }
                }
            }
            __syncthreads();
        }
    }
}

// ---------------------------------------------------------------------------
extern "C" void kernel_launch(void* const* d_in, const int* in_sizes, int n_in,
                              void* d_out, int out_size) {
    const float* x = (const float*)d_in[0];
    P12 p;
    if (n_in >= 13 && in_sizes[3] == 196608) {
        // signature order: Wf,bf, Wi,bi, Wu,bu, Wo,bo, rf,ri,ru,ro
        for (int g = 0; g < 4; g++) {
            p.W[g] = (const float*)d_in[1 + 2 * g];
            p.B[g] = (const float*)d_in[2 + 2 * g];
            p.R[g] = (const float*)d_in[9 + g];
        }
    } else {
        // dict order: (W,b,r) per gate
        for (int g = 0; g < 4; g++) {
            p.W[g] = (const float*)d_in[1 + 3 * g];
            p.B[g] = (const float*)d_in[2 + 3 * g];
            p.R[g] = (const float*)d_in[3 + 3 * g];
        }
    }

    g1_kernel<<<dim3(8, 1024), 256>>>(x, p);

    cudaFuncSetAttribute(rnn_kernel, cudaFuncAttributeMaxDynamicSharedMemorySize, 102400);
    rnn_kernel<<<dim3(16, 8), 256, 98560>>>(p, (float*)d_out, out_size);
}

// round 6
// speedup vs baseline: 1.3859x; 1.2608x over previous
#include <cuda_runtime.h>
#include <cuda_bf16.h>
#include <cstdint>

typedef unsigned long long ull;

struct P12 { const float* W[4]; const float* B[4]; const float* R[4]; };

// ---------------- persistent device scratch (no allocations allowed) --------
__device__ float g_X[(size_t)512 * 256 * 1024];         // pre-activations [t][b][g*256+u]
__device__ float g_h[2][256 * 256];                     // ping-pong h
__device__ unsigned g_cnt[8];
__device__ volatile unsigned g_gen[8];
__device__ __nv_bfloat16 g_Ahi[(size_t)131072 * 512];   // x hi
__device__ __nv_bfloat16 g_Alo[(size_t)131072 * 512];   // x lo
__device__ __nv_bfloat16 g_Whi[1024 * 512];             // W (input cols) hi, rows n=g*256+u
__device__ __nv_bfloat16 g_Wlo[1024 * 512];

// ---------------- helpers ----------------------------------------------------
__device__ __forceinline__ ull pk(float x, float y) {
    ull r; asm("mov.b64 %0, {%1,%2};" : "=l"(r) : "f"(x), "f"(y)); return r;
}
__device__ __forceinline__ void fma2(ull& d, ull a, ull b) {
    asm("fma.rn.f32x2 %0, %1, %2, %0;" : "+l"(d) : "l"(a), "l"(b));
}
__device__ __forceinline__ float lane_sum(ull v) {
    float x, y; asm("mov.b64 {%0,%1}, %2;" : "=f"(x), "=f"(y) : "l"(v)); return x + y;
}
__device__ __forceinline__ float sigm(float x) { return 1.f / (1.f + __expf(-x)); }

__device__ __forceinline__ uint32_t smem_u32(const void* p) {
    uint32_t a; asm("{ .reg .u64 t; cvta.to.shared.u64 t, %1; cvt.u32.u64 %0, t; }"
                    : "=r"(a) : "l"(p)); return a;
}
#define SWZ(x) ((x) ^ (((x) >> 3) & 0x70))

__device__ __forceinline__ void ldsm_x4(uint32_t& r0, uint32_t& r1, uint32_t& r2,
                                        uint32_t& r3, uint32_t addr) {
    asm volatile("ldmatrix.sync.aligned.m8n8.x4.shared.b16 {%0,%1,%2,%3}, [%4];"
                 : "=r"(r0), "=r"(r1), "=r"(r2), "=r"(r3) : "r"(addr));
}
__device__ __forceinline__ void mma16816(float* d, const uint32_t* a,
                                         uint32_t b0, uint32_t b1) {
    asm volatile("mma.sync.aligned.m16n8k16.row.col.f32.bf16.bf16.f32 "
                 "{%0,%1,%2,%3}, {%4,%5,%6,%7}, {%8,%9}, {%0,%1,%2,%3};"
                 : "+f"(d[0]), "+f"(d[1]), "+f"(d[2]), "+f"(d[3])
                 : "r"(a[0]), "r"(a[1]), "r"(a[2]), "r"(a[3]), "r"(b0), "r"(b1));
}

// ---------------------------------------------------------------------------
// Conversion kernels: fp32 -> bf16 hi/lo split
// ---------------------------------------------------------------------------
__global__ void cvtA_kernel(const float* __restrict__ A) {
    size_t i = (size_t)blockIdx.x * blockDim.x + threadIdx.x;
    size_t n = (size_t)131072 * 512;
    for (; i < n; i += (size_t)gridDim.x * blockDim.x) {
        float v = A[i];
        __nv_bfloat16 h = __float2bfloat16(v);
        g_Ahi[i] = h;
        g_Alo[i] = __float2bfloat16(v - __bfloat162float(h));
    }
}
__global__ void cvtW_kernel(P12 p) {
    int i = blockIdx.x * blockDim.x + threadIdx.x;
    if (i >= 1024 * 512) return;
    int nrow = i >> 9, k = i & 511;
    int g = nrow >> 8, u = nrow & 255;
    float v = p.W[g][(size_t)u * 768 + k];
    __nv_bfloat16 h = __float2bfloat16(v);
    g_Whi[i] = h;
    g_Wlo[i] = __float2bfloat16(v - __bfloat162float(h));
}

// ---------------------------------------------------------------------------
// Kernel 1 (mma.sync bf16): X[m][n] = x[m] . W[n] + (b+r)[n]
//   CTA: M=128, N=128, K=512, 3 bf16-split passes = 24 chunks of K=64.
//   8 warps (2m x 4n), warp tile 64x32, double-buffered swizzled SMEM.
// ---------------------------------------------------------------------------
__global__ void __launch_bounds__(256, 1) g1mma_kernel(P12 p) {
    extern __shared__ __align__(1024) char sh[];
    // buf s: A at s*32768 (128 rows x 128B), B at s*32768 + 16384
    uint32_t sb = smem_u32(sh);
    const int tid = threadIdx.x, wid = tid >> 5, lane = tid & 31;
    const int n0 = blockIdx.x * 128, m0 = blockIdx.y * 128;
    const int gate = n0 >> 8, ub = n0 & 255;
    const int mw = (wid >> 2) * 64, nw = (wid & 3) * 32;

    const __nv_bfloat16* Asrc[3] = { g_Ahi, g_Alo, g_Ahi };
    const __nv_bfloat16* Bsrc[3] = { g_Whi, g_Whi, g_Wlo };

    float d[4][4][4];
#pragma unroll
    for (int i = 0; i < 4; i++)
#pragma unroll
        for (int j = 0; j < 4; j++)
#pragma unroll
            for (int q = 0; q < 4; q++) d[i][j][q] = 0.f;

    uint4 ra[4], rb[4];
    const int lrow = tid >> 3, lj = tid & 7;  // per-thread 16B slot (rows 0..31 base)

    auto ldg = [&](int c) {
        int sp = c >> 3, kc = (c & 7) << 6;
        const __nv_bfloat16* Ap = Asrc[sp] + (size_t)m0 * 512 + kc;
        const __nv_bfloat16* Bp = Bsrc[sp] + (size_t)n0 * 512 + kc;
#pragma unroll
        for (int it = 0; it < 4; it++) {
            int row = lrow + 32 * it;
            ra[it] = *(const uint4*)(Ap + (size_t)row * 512 + lj * 8);
            rb[it] = *(const uint4*)(Bp + (size_t)row * 512 + lj * 8);
        }
    };
    auto sts = [&](int s) {
        char* at = sh + s * 32768;
        char* bt = at + 16384;
#pragma unroll
        for (int it = 0; it < 4; it++) {
            int row = lrow + 32 * it;
            uint32_t off = SWZ((uint32_t)(row * 128 + lj * 16));
            *(uint4*)(at + off) = ra[it];
            *(uint4*)(bt + off) = rb[it];
        }
    };

    ldg(0); sts(0);
    __syncthreads();

    for (int c = 0; c < 24; c++) {
        const int s = c & 1;
        if (c < 23) ldg(c + 1);
        const uint32_t sA = sb + s * 32768, sB = sA + 16384;
#pragma unroll
        for (int k16 = 0; k16 < 4; k16++) {
            const uint32_t colb = k16 * 32 + ((lane >> 4) << 4);
            uint32_t a[4][4], b[2][4];
#pragma unroll
            for (int im = 0; im < 4; im++) {
                int r = mw + im * 16 + (lane & 15);
                ldsm_x4(a[im][0], a[im][1], a[im][2], a[im][3],
                        sA + SWZ((uint32_t)(r * 128 + colb)));
            }
#pragma unroll
            for (int jn = 0; jn < 2; jn++) {
                int r = nw + jn * 16 + (lane & 15);
                ldsm_x4(b[jn][0], b[jn][1], b[jn][2], b[jn][3],
                        sB + SWZ((uint32_t)(r * 128 + colb)));
            }
#pragma unroll
            for (int im = 0; im < 4; im++)
#pragma unroll
                for (int j = 0; j < 4; j++)
                    mma16816(d[im][j], a[im], b[j >> 1][j & 1], b[j >> 1][2 + (j & 1)]);
        }
        if (c < 23) {
            sts(s ^ 1);
            __syncthreads();
        }
    }

    // epilogue: registers -> g_X with bias+rot add (float2 stores, 32B sectors)
#pragma unroll
    for (int j = 0; j < 4; j++) {
        int nl = nw + j * 8 + (lane & 3) * 2;
        int u = ub + nl;
        float bv0 = p.B[gate][u] + p.R[gate][u];
        float bv1 = p.B[gate][u + 1] + p.R[gate][u + 1];
#pragma unroll
        for (int im = 0; im < 4; im++) {
            int m = m0 + mw + im * 16 + (lane >> 2);
            float2 v0 = { d[im][j][0] + bv0, d[im][j][1] + bv1 };
            float2 v1 = { d[im][j][2] + bv0, d[im][j][3] + bv1 };
            *(float2*)(g_X + (size_t)m * 1024 + n0 + nl) = v0;
            *(float2*)(g_X + (size_t)(m + 8) * 1024 + n0 + nl) = v1;
        }
    }
}

// ---------------------------------------------------------------------------
// Kernel 2: persistent recurrence. Grid (16 unit-tiles, 8 batch-groups),
// 256 threads. CTA: units u0..u0+15 (all 4 gates, c in regs), batches
// b0..b0+31. Wh slice resident in SMEM (LDS.128 k2-pair loads).
// ---------------------------------------------------------------------------
__global__ void __launch_bounds__(256, 1) rnn_kernel(P12 p, float* __restrict__ out,
                                                     int out_elems) {
    extern __shared__ ulonglong2 sh2[];
    ulonglong2* WS2 = sh2;          // [64 k22][64 r] (r = gate*16+ui), x=even k2, y=odd
    ulonglong2* HS2 = sh2 + 4096;   // [32 b][65] padded

    const int tid = threadIdx.x, tn = tid & 15, tm = tid >> 4;  // tm 0..15
    const int u0 = blockIdx.x * 16, bb = blockIdx.y, b0 = bb * 32;
    const int unit = u0 + tn;

    for (int idx = tid; idx < 4096; idx += 256) {
        int r = idx & 63, k22 = idx >> 6;
        int g = r >> 4, ui = r & 15;
        const float* wp = p.W[g] + (size_t)(u0 + ui) * 768 + 512 + 4 * k22;
        WS2[idx] = make_ulonglong2(pk(wp[0], wp[1]), pk(wp[2], wp[3]));
    }
    __shared__ unsigned s_gen0;
    if (tid == 0) s_gen0 = g_gen[bb];
    __syncthreads();
    const unsigned gen0 = s_gen0;

    float c[2] = {0.f, 0.f};

    for (int t = 0; t < 512; t++) {
        ull acc[2][4];
        const float* Xt = g_X + (size_t)t * 256 * 1024;
#pragma unroll
        for (int i = 0; i < 2; i++) {
            int b = b0 + tm + 16 * i;
#pragma unroll
            for (int j = 0; j < 4; j++)
                acc[i][j] = (ull)__float_as_uint(Xt[(size_t)b * 1024 + j * 256 + unit]);
        }

        if (t > 0) {
            const float4* hsrc = (const float4*)g_h[(t + 1) & 1];
#pragma unroll
            for (int i = 0; i < 8; i++) {
                int idx = tid + 256 * i;
                int bi = idx >> 6, q = idx & 63;
                float4 v = __ldcg(hsrc + (size_t)(b0 + bi) * 64 + q);
                HS2[bi * 65 + q] = make_ulonglong2(pk(v.x, v.y), pk(v.z, v.w));
            }
            __syncthreads();
#pragma unroll 8
            for (int k22 = 0; k22 < 64; k22++) {
                ulonglong2 a0 = HS2[tm * 65 + k22];
                ulonglong2 a1 = HS2[(tm + 16) * 65 + k22];
                ulonglong2 w0 = WS2[k22 * 64 + tn];
                ulonglong2 w1 = WS2[k22 * 64 + tn + 16];
                ulonglong2 w2 = WS2[k22 * 64 + tn + 32];
                ulonglong2 w3 = WS2[k22 * 64 + tn + 48];
                fma2(acc[0][0], a0.x, w0.x); fma2(acc[0][0], a0.y, w0.y);
                fma2(acc[0][1], a0.x, w1.x); fma2(acc[0][1], a0.y, w1.y);
                fma2(acc[0][2], a0.x, w2.x); fma2(acc[0][2], a0.y, w2.y);
                fma2(acc[0][3], a0.x, w3.x); fma2(acc[0][3], a0.y, w3.y);
                fma2(acc[1][0], a1.x, w0.x); fma2(acc[1][0], a1.y, w0.y);
                fma2(acc[1][1], a1.x, w1.x); fma2(acc[1][1], a1.y, w1.y);
                fma2(acc[1][2], a1.x, w2.x); fma2(acc[1][2], a1.y, w2.y);
                fma2(acc[1][3], a1.x, w3.x); fma2(acc[1][3], a1.y, w3.y);
            }
        }

        float* hdst = g_h[t & 1];
#pragma unroll
        for (int i = 0; i < 2; i++) {
            float pf = sigm(lane_sum(acc[i][0]));
            float pi = sigm(lane_sum(acc[i][1]));
            float pu = sigm(lane_sum(acc[i][2]));
            float po = sigm(lane_sum(acc[i][3]));
            c[i] = pf * c[i] + pi * pu;
            float h = po * tanhf(c[i]);
            int b = b0 + tm + 16 * i;
            out[(size_t)t * 65536 + b * 256 + unit] = h;
            hdst[b * 256 + unit] = h;
            if (t == 511 && out_elems >= 33685504) {
                out[33554432 + b * 256 + unit] = h;      // hx
                out[33619968 + b * 256 + unit] = c[i];   // cx
            }
        }

        if (t < 511) {
            __threadfence();
            __syncthreads();
            if (tid == 0) {
                unsigned want = gen0 + (unsigned)t + 1u;
                unsigned a = atomicAdd(&g_cnt[bb], 1u);
                if (a == 15u) {
                    g_cnt[bb] = 0u;
                    __threadfence();
                    g_gen[bb] = want;
                } else {
                    while ((int)(g_gen[bb] - want) < 0) { }
                }
            }
            __syncthreads();
        }
    }
}

// ---------------------------------------------------------------------------
extern "C" void kernel_launch(void* const* d_in, const int* in_sizes, int n_in,
                              void* d_out, int out_size) {
    const float* x = (const float*)d_in[0];
    P12 p;
    if (n_in >= 13 && in_sizes[3] == 196608) {
        for (int g = 0; g < 4; g++) {
            p.W[g] = (const float*)d_in[1 + 2 * g];
            p.B[g] = (const float*)d_in[2 + 2 * g];
            p.R[g] = (const float*)d_in[9 + g];
        }
    } else {
        for (int g = 0; g < 4; g++) {
            p.W[g] = (const float*)d_in[1 + 3 * g];
            p.B[g] = (const float*)d_in[2 + 3 * g];
            p.R[g] = (const float*)d_in[3 + 3 * g];
        }
    }

    cvtA_kernel<<<4096, 256>>>(x);
    cvtW_kernel<<<2048, 256>>>(p);

    cudaFuncSetAttribute(g1mma_kernel, cudaFuncAttributeMaxDynamicSharedMemorySize, 65536);
    g1mma_kernel<<<dim3(8, 1024), 256, 65536>>>(p);

    cudaFuncSetAttribute(rnn_kernel, cudaFuncAttributeMaxDynamicSharedMemorySize, 102400);
    rnn_kernel<<<dim3(16, 8), 256, 99072>>>(p, (float*)d_out, out_size);
}

// round 7
// speedup vs baseline: 1.5574x; 1.1237x over previous
#include <cuda_runtime.h>
#include <cuda_bf16.h>
#include <cstdint>

typedef unsigned long long ull;

struct P12 { const float* W[4]; const float* B[4]; const float* R[4]; };

// ---------------- persistent device scratch (no allocations allowed) --------
__device__ float g_X[(size_t)512 * 256 * 1024];         // pre-activations [t][b][g*256+u]
__device__ float g_h[2][256 * 256];                     // ping-pong h
__device__ unsigned g_flags[128 * 32];                  // per-CTA barrier flags (128B apart)
__device__ __nv_bfloat16 g_Ahi[(size_t)131072 * 512];   // x hi
__device__ __nv_bfloat16 g_Alo[(size_t)131072 * 512];   // x lo
__device__ __nv_bfloat16 g_Whi[1024 * 512];             // W (input cols) hi
__device__ __nv_bfloat16 g_Wlo[1024 * 512];

// ---------------- helpers ----------------------------------------------------
__device__ __forceinline__ ull pk(float x, float y) {
    ull r; asm("mov.b64 %0, {%1,%2};" : "=l"(r) : "f"(x), "f"(y)); return r;
}
__device__ __forceinline__ void fma2(ull& d, ull a, ull b) {
    asm("fma.rn.f32x2 %0, %1, %2, %0;" : "+l"(d) : "l"(a), "l"(b));
}
__device__ __forceinline__ float lane_sum(ull v) {
    float x, y; asm("mov.b64 {%0,%1}, %2;" : "=f"(x), "=f"(y) : "l"(v)); return x + y;
}
__device__ __forceinline__ float ex2a(float x) {
    float r; asm("ex2.approx.f32 %0, %1;" : "=f"(r) : "f"(x)); return r;
}
__device__ __forceinline__ float rcpa(float x) {
    float r; asm("rcp.approx.f32 %0, %1;" : "=f"(r) : "f"(x)); return r;
}
__device__ __forceinline__ float sigm_fast(float x) {
    return rcpa(1.0f + ex2a(-1.4426950408889634f * x));
}
__device__ __forceinline__ float tanh_fast(float x) {
    return 1.0f - 2.0f * rcpa(1.0f + ex2a(2.8853900817779268f * x));
}
__device__ __forceinline__ uint32_t smem_u32(const void* p) {
    uint32_t a; asm("{ .reg .u64 t; cvta.to.shared.u64 t, %1; cvt.u32.u64 %0, t; }"
                    : "=r"(a) : "l"(p)); return a;
}
__device__ __forceinline__ void st_release(unsigned* p, unsigned v) {
    asm volatile("st.release.gpu.u32 [%0], %1;" :: "l"(p), "r"(v) : "memory");
}
__device__ __forceinline__ unsigned ld_acquire(const unsigned* p) {
    unsigned v; asm volatile("ld.acquire.gpu.u32 %0, [%1];" : "=r"(v) : "l"(p) : "memory");
    return v;
}
#define SWZ(x) ((x) ^ (((x) >> 3) & 0x70))

__device__ __forceinline__ void ldsm_x4(uint32_t& r0, uint32_t& r1, uint32_t& r2,
                                        uint32_t& r3, uint32_t addr) {
    asm volatile("ldmatrix.sync.aligned.m8n8.x4.shared.b16 {%0,%1,%2,%3}, [%4];"
                 : "=r"(r0), "=r"(r1), "=r"(r2), "=r"(r3) : "r"(addr));
}
__device__ __forceinline__ void mma16816(float* d, const uint32_t* a,
                                         uint32_t b0, uint32_t b1) {
    asm volatile("mma.sync.aligned.m16n8k16.row.col.f32.bf16.bf16.f32 "
                 "{%0,%1,%2,%3}, {%4,%5,%6,%7}, {%8,%9}, {%0,%1,%2,%3};"
                 : "+f"(d[0]), "+f"(d[1]), "+f"(d[2]), "+f"(d[3])
                 : "r"(a[0]), "r"(a[1]), "r"(a[2]), "r"(a[3]), "r"(b0), "r"(b1));
}

// ---------------------------------------------------------------------------
// Conversion kernels: fp32 -> bf16 hi/lo split
// ---------------------------------------------------------------------------
__global__ void cvtA_kernel(const float* __restrict__ A) {
    size_t i = (size_t)blockIdx.x * blockDim.x + threadIdx.x;
    size_t n = (size_t)131072 * 512;
    for (; i < n; i += (size_t)gridDim.x * blockDim.x) {
        float v = A[i];
        __nv_bfloat16 h = __float2bfloat16(v);
        g_Ahi[i] = h;
        g_Alo[i] = __float2bfloat16(v - __bfloat162float(h));
    }
}
__global__ void cvtW_kernel(P12 p) {
    int i = blockIdx.x * blockDim.x + threadIdx.x;
    if (i >= 1024 * 512) return;
    int nrow = i >> 9, k = i & 511;
    int g = nrow >> 8, u = nrow & 255;
    float v = p.W[g][(size_t)u * 768 + k];
    __nv_bfloat16 h = __float2bfloat16(v);
    g_Whi[i] = h;
    g_Wlo[i] = __float2bfloat16(v - __bfloat162float(h));
}

// ---------------------------------------------------------------------------
// Kernel 1 (mma.sync bf16): X[m][n] = x[m] . W[n] + (b+r)[n]
//   CTA: M=128, N=128, K=512, 3 bf16-split passes = 24 chunks of K=64.
// ---------------------------------------------------------------------------
__global__ void __launch_bounds__(256, 1) g1mma_kernel(P12 p) {
    extern __shared__ __align__(1024) char sh[];
    uint32_t sb = smem_u32(sh);
    const int tid = threadIdx.x, wid = tid >> 5, lane = tid & 31;
    const int n0 = blockIdx.x * 128, m0 = blockIdx.y * 128;
    const int gate = n0 >> 8, ub = n0 & 255;
    const int mw = (wid >> 2) * 64, nw = (wid & 3) * 32;

    const __nv_bfloat16* Asrc[3] = { g_Ahi, g_Alo, g_Ahi };
    const __nv_bfloat16* Bsrc[3] = { g_Whi, g_Whi, g_Wlo };

    float d[4][4][4];
#pragma unroll
    for (int i = 0; i < 4; i++)
#pragma unroll
        for (int j = 0; j < 4; j++)
#pragma unroll
            for (int q = 0; q < 4; q++) d[i][j][q] = 0.f;

    uint4 ra[4], rb[4];
    const int lrow = tid >> 3, lj = tid & 7;

    auto ldg = [&](int c) {
        int sp = c >> 3, kc = (c & 7) << 6;
        const __nv_bfloat16* Ap = Asrc[sp] + (size_t)m0 * 512 + kc;
        const __nv_bfloat16* Bp = Bsrc[sp] + (size_t)n0 * 512 + kc;
#pragma unroll
        for (int it = 0; it < 4; it++) {
            int row = lrow + 32 * it;
            ra[it] = *(const uint4*)(Ap + (size_t)row * 512 + lj * 8);
            rb[it] = *(const uint4*)(Bp + (size_t)row * 512 + lj * 8);
        }
    };
    auto sts = [&](int s) {
        char* at = sh + s * 32768;
        char* bt = at + 16384;
#pragma unroll
        for (int it = 0; it < 4; it++) {
            int row = lrow + 32 * it;
            uint32_t off = SWZ((uint32_t)(row * 128 + lj * 16));
            *(uint4*)(at + off) = ra[it];
            *(uint4*)(bt + off) = rb[it];
        }
    };

    ldg(0); sts(0);
    __syncthreads();

    for (int c = 0; c < 24; c++) {
        const int s = c & 1;
        if (c < 23) ldg(c + 1);
        const uint32_t sA = sb + s * 32768, sB = sA + 16384;
#pragma unroll
        for (int k16 = 0; k16 < 4; k16++) {
            const uint32_t colb = k16 * 32 + ((lane >> 4) << 4);
            uint32_t a[4][4], b[2][4];
#pragma unroll
            for (int im = 0; im < 4; im++) {
                int r = mw + im * 16 + (lane & 15);
                ldsm_x4(a[im][0], a[im][1], a[im][2], a[im][3],
                        sA + SWZ((uint32_t)(r * 128 + colb)));
            }
#pragma unroll
            for (int jn = 0; jn < 2; jn++) {
                int r = nw + jn * 16 + (lane & 15);
                ldsm_x4(b[jn][0], b[jn][1], b[jn][2], b[jn][3],
                        sB + SWZ((uint32_t)(r * 128 + colb)));
            }
#pragma unroll
            for (int im = 0; im < 4; im++)
#pragma unroll
                for (int j = 0; j < 4; j++)
                    mma16816(d[im][j], a[im], b[j >> 1][j & 1], b[j >> 1][2 + (j & 1)]);
        }
        if (c < 23) {
            sts(s ^ 1);
            __syncthreads();
        }
    }

#pragma unroll
    for (int j = 0; j < 4; j++) {
        int nl = nw + j * 8 + (lane & 3) * 2;
        int u = ub + nl;
        float bv0 = p.B[gate][u] + p.R[gate][u];
        float bv1 = p.B[gate][u + 1] + p.R[gate][u + 1];
#pragma unroll
        for (int im = 0; im < 4; im++) {
            int m = m0 + mw + im * 16 + (lane >> 2);
            float2 v0 = { d[im][j][0] + bv0, d[im][j][1] + bv1 };
            float2 v1 = { d[im][j][2] + bv0, d[im][j][3] + bv1 };
            *(float2*)(g_X + (size_t)m * 1024 + n0 + nl) = v0;
            *(float2*)(g_X + (size_t)(m + 8) * 1024 + n0 + nl) = v1;
        }
    }
}

// ---------------------------------------------------------------------------
// Kernel 2: persistent recurrence. Grid (16 unit-tiles, 8 batch-groups),
// 256 threads. Flag barrier (release/acquire), X prefetch, approx gates.
// ---------------------------------------------------------------------------
__global__ void __launch_bounds__(256, 1) rnn_kernel(P12 p, float* __restrict__ out,
                                                     int out_elems) {
    extern __shared__ ulonglong2 sh2[];
    ulonglong2* WS2 = sh2;          // [64 k22][64 r] (r = gate*16+ui)
    ulonglong2* HS2 = sh2 + 4096;   // [32 b][65] padded

    const int tid = threadIdx.x, tn = tid & 15, tm = tid >> 4;  // tm 0..15
    const int u0 = blockIdx.x * 16, bb = blockIdx.y, b0 = bb * 32;
    const int unit = u0 + tn;
    const int myflag = bb * 16 + blockIdx.x;

    for (int idx = tid; idx < 4096; idx += 256) {
        int r = idx & 63, k22 = idx >> 6;
        int g = r >> 4, ui = r & 15;
        const float* wp = p.W[g] + (size_t)(u0 + ui) * 768 + 512 + 4 * k22;
        WS2[idx] = make_ulonglong2(pk(wp[0], wp[1]), pk(wp[2], wp[3]));
    }
    __shared__ unsigned s_gen0;
    if (tid == 0) s_gen0 = g_flags[myflag * 32];
    __syncthreads();
    const unsigned gen0 = s_gen0;

    float c[2] = {0.f, 0.f};
    const size_t xoff = (size_t)(b0 + tm) * 1024 + unit;

    // prefetch X(0)
    float xpre[8];
    {
        const float* Xn = g_X + xoff;
#pragma unroll
        for (int i = 0; i < 2; i++)
#pragma unroll
            for (int j = 0; j < 4; j++)
                xpre[i * 4 + j] = __ldcs(Xn + (size_t)i * 16384 + j * 256);
    }

    for (int t = 0; t < 512; t++) {
        ull acc[2][4];
#pragma unroll
        for (int i = 0; i < 2; i++)
#pragma unroll
            for (int j = 0; j < 4; j++)
                acc[i][j] = (ull)__float_as_uint(xpre[i * 4 + j]);

        if (t > 0) {
            const float4* hsrc = (const float4*)g_h[(t + 1) & 1];
#pragma unroll
            for (int i = 0; i < 8; i++) {
                int idx = tid + 256 * i;
                int bi = idx >> 6, q = idx & 63;
                float4 v = __ldcg(hsrc + (size_t)(b0 + bi) * 64 + q);
                HS2[bi * 65 + q] = make_ulonglong2(pk(v.x, v.y), pk(v.z, v.w));
            }
            __syncthreads();
        }

        // prefetch X(t+1) — in flight during k-loop + barrier
        if (t < 511) {
            const float* Xn = g_X + ((size_t)(t + 1) << 18) + xoff;
#pragma unroll
            for (int i = 0; i < 2; i++)
#pragma unroll
                for (int j = 0; j < 4; j++)
                    xpre[i * 4 + j] = __ldcs(Xn + (size_t)i * 16384 + j * 256);
        }

        if (t > 0) {
#pragma unroll 8
            for (int k22 = 0; k22 < 64; k22++) {
                ulonglong2 a0 = HS2[tm * 65 + k22];
                ulonglong2 a1 = HS2[(tm + 16) * 65 + k22];
                ulonglong2 w0 = WS2[k22 * 64 + tn];
                ulonglong2 w1 = WS2[k22 * 64 + tn + 16];
                ulonglong2 w2 = WS2[k22 * 64 + tn + 32];
                ulonglong2 w3 = WS2[k22 * 64 + tn + 48];
                fma2(acc[0][0], a0.x, w0.x); fma2(acc[0][0], a0.y, w0.y);
                fma2(acc[0][1], a0.x, w1.x); fma2(acc[0][1], a0.y, w1.y);
                fma2(acc[0][2], a0.x, w2.x); fma2(acc[0][2], a0.y, w2.y);
                fma2(acc[0][3], a0.x, w3.x); fma2(acc[0][3], a0.y, w3.y);
                fma2(acc[1][0], a1.x, w0.x); fma2(acc[1][0], a1.y, w0.y);
                fma2(acc[1][1], a1.x, w1.x); fma2(acc[1][1], a1.y, w1.y);
                fma2(acc[1][2], a1.x, w2.x); fma2(acc[1][2], a1.y, w2.y);
                fma2(acc[1][3], a1.x, w3.x); fma2(acc[1][3], a1.y, w3.y);
            }
        }

        // gates
        float hval[2];
        float* hdst = g_h[t & 1];
#pragma unroll
        for (int i = 0; i < 2; i++) {
            float pf = sigm_fast(lane_sum(acc[i][0]));
            float pi = sigm_fast(lane_sum(acc[i][1]));
            float pu = sigm_fast(lane_sum(acc[i][2]));
            float po = sigm_fast(lane_sum(acc[i][3]));
            c[i] = pf * c[i] + pi * pu;
            hval[i] = po * tanh_fast(c[i]);
            int b = b0 + tm + 16 * i;
            hdst[b * 256 + unit] = hval[i];
        }

        if (t < 511) {
            __syncthreads();                       // all h stores issued
            if (tid == 0)
                st_release(&g_flags[myflag * 32], gen0 + (unsigned)t + 1u);
            // out[] stores overlap the barrier (never read by other CTAs)
#pragma unroll
            for (int i = 0; i < 2; i++) {
                int b = b0 + tm + 16 * i;
                out[(size_t)t * 65536 + b * 256 + unit] = hval[i];
            }
            if (tid < 16) {
                const unsigned* fp = &g_flags[(bb * 16 + tid) * 32];
                unsigned want = gen0 + (unsigned)t + 1u;
                while ((int)(ld_acquire(fp) - want) < 0) { }
            }
            __syncthreads();
        } else {
#pragma unroll
            for (int i = 0; i < 2; i++) {
                int b = b0 + tm + 16 * i;
                out[(size_t)t * 65536 + b * 256 + unit] = hval[i];
                if (out_elems >= 33685504) {
                    out[33554432 + b * 256 + unit] = hval[i];  // hx
                    out[33619968 + b * 256 + unit] = c[i];     // cx
                }
            }
        }
    }
}

// ---------------------------------------------------------------------------
extern "C" void kernel_launch(void* const* d_in, const int* in_sizes, int n_in,
                              void* d_out, int out_size) {
    const float* x = (const float*)d_in[0];
    P12 p;
    if (n_in >= 13 && in_sizes[3] == 196608) {
        for (int g = 0; g < 4; g++) {
            p.W[g] = (const float*)d_in[1 + 2 * g];
            p.B[g] = (const float*)d_in[2 + 2 * g];
            p.R[g] = (const float*)d_in[9 + g];
        }
    } else {
        for (int g = 0; g < 4; g++) {
            p.W[g] = (const float*)d_in[1 + 3 * g];
            p.B[g] = (const float*)d_in[2 + 3 * g];
            p.R[g] = (const float*)d_in[3 + 3 * g];
        }
    }

    cvtA_kernel<<<4096, 256>>>(x);
    cvtW_kernel<<<2048, 256>>>(p);

    cudaFuncSetAttribute(g1mma_kernel, cudaFuncAttributeMaxDynamicSharedMemorySize, 65536);
    g1mma_kernel<<<dim3(8, 1024), 256, 65536>>>(p);

    cudaFuncSetAttribute(rnn_kernel, cudaFuncAttributeMaxDynamicSharedMemorySize, 102400);
    rnn_kernel<<<dim3(16, 8), 256, 99072>>>(p, (float*)d_out, out_size);
}

// round 8
// speedup vs baseline: 1.6440x; 1.0556x over previous
#include <cuda_runtime.h>
#include <cuda_bf16.h>
#include <cstdint>

typedef unsigned long long ull;

struct P12 { const float* W[4]; const float* B[4]; const float* R[4]; };

// ---------------- persistent device scratch (no allocations allowed) --------
__device__ float g_X[(size_t)512 * 256 * 1024];   // pre-activations [t][b][g*256+u]
__device__ float g_h[2][256 * 256];               // ping-pong h
__device__ unsigned g_flags[128 * 32];            // per-CTA barrier flags (128B apart)
__device__ __nv_bfloat16 g_Whi[1024 * 512];       // W (input cols) hi
__device__ __nv_bfloat16 g_Wlo[1024 * 512];

// ---------------- helpers ----------------------------------------------------
__device__ __forceinline__ ull pk(float x, float y) {
    ull r; asm("mov.b64 %0, {%1,%2};" : "=l"(r) : "f"(x), "f"(y)); return r;
}
__device__ __forceinline__ void fma2(ull& d, ull a, ull b) {
    asm("fma.rn.f32x2 %0, %1, %2, %0;" : "+l"(d) : "l"(a), "l"(b));
}
__device__ __forceinline__ float lane_sum(ull v) {
    float x, y; asm("mov.b64 {%0,%1}, %2;" : "=f"(x), "=f"(y) : "l"(v)); return x + y;
}
__device__ __forceinline__ float ex2a(float x) {
    float r; asm("ex2.approx.f32 %0, %1;" : "=f"(r) : "f"(x)); return r;
}
__device__ __forceinline__ float rcpa(float x) {
    float r; asm("rcp.approx.f32 %0, %1;" : "=f"(r) : "f"(x)); return r;
}
__device__ __forceinline__ float sigm_fast(float x) {
    return rcpa(1.0f + ex2a(-1.4426950408889634f * x));
}
__device__ __forceinline__ float tanh_fast(float x) {
    return 1.0f - 2.0f * rcpa(1.0f + ex2a(2.8853900817779268f * x));
}
__device__ __forceinline__ uint32_t smem_u32(const void* p) {
    uint32_t a; asm("{ .reg .u64 t; cvta.to.shared.u64 t, %1; cvt.u32.u64 %0, t; }"
                    : "=r"(a) : "l"(p)); return a;
}
__device__ __forceinline__ void st_release(unsigned* p, unsigned v) {
    asm volatile("st.release.gpu.u32 [%0], %1;" :: "l"(p), "r"(v) : "memory");
}
__device__ __forceinline__ unsigned ld_acquire(const unsigned* p) {
    unsigned v; asm volatile("ld.acquire.gpu.u32 %0, [%1];" : "=r"(v) : "l"(p) : "memory");
    return v;
}
__device__ __forceinline__ uint32_t bfhi2(float a, float b) {
    __nv_bfloat162 h = __float22bfloat162_rn(make_float2(a, b));
    return *reinterpret_cast<uint32_t*>(&h);
}
__device__ __forceinline__ uint32_t bflo2(float a, float b) {
    __nv_bfloat162 h = __float22bfloat162_rn(make_float2(a, b));
    float2 hf = __bfloat1622float2(h);
    __nv_bfloat162 l = __float22bfloat162_rn(make_float2(a - hf.x, b - hf.y));
    return *reinterpret_cast<uint32_t*>(&l);
}
#define SWZ(x) ((x) ^ (((x) >> 3) & 0x70))

__device__ __forceinline__ void ldsm_x4(uint32_t& r0, uint32_t& r1, uint32_t& r2,
                                        uint32_t& r3, uint32_t addr) {
    asm volatile("ldmatrix.sync.aligned.m8n8.x4.shared.b16 {%0,%1,%2,%3}, [%4];"
                 : "=r"(r0), "=r"(r1), "=r"(r2), "=r"(r3) : "r"(addr));
}
__device__ __forceinline__ void mma16816(float* d, const uint32_t* a,
                                         uint32_t b0, uint32_t b1) {
    asm volatile("mma.sync.aligned.m16n8k16.row.col.f32.bf16.bf16.f32 "
                 "{%0,%1,%2,%3}, {%4,%5,%6,%7}, {%8,%9}, {%0,%1,%2,%3};"
                 : "+f"(d[0]), "+f"(d[1]), "+f"(d[2]), "+f"(d[3])
                 : "r"(a[0]), "r"(a[1]), "r"(a[2]), "r"(a[3]), "r"(b0), "r"(b1));
}

// ---------------------------------------------------------------------------
// W conversion: fp32 -> bf16 hi/lo split (x conversion fused into g1mma)
// ---------------------------------------------------------------------------
__global__ void cvtW_kernel(P12 p) {
    int i = blockIdx.x * blockDim.x + threadIdx.x;
    if (i >= 1024 * 512) return;
    int nrow = i >> 9, k = i & 511;
    int g = nrow >> 8, u = nrow & 255;
    float v = p.W[g][(size_t)u * 768 + k];
    __nv_bfloat16 h = __float2bfloat16(v);
    g_Whi[i] = h;
    g_Wlo[i] = __float2bfloat16(v - __bfloat162float(h));
}

// ---------------------------------------------------------------------------
// Kernel 1 (mma.sync bf16): X[m][n] = x[m] . W[n] + (b+r)[n]
//   CTA: M=128, N=128, K=512, 3 bf16-split passes (hi.hi + lo.hi + hi.lo)
//   = 24 chunks of K=64. x converted fp32->bf16 hi/lo on the fly.
// ---------------------------------------------------------------------------
__global__ void __launch_bounds__(256, 1) g1mma_kernel(const float* __restrict__ Ax, P12 p) {
    extern __shared__ __align__(1024) char sh[];
    uint32_t sb = smem_u32(sh);
    const int tid = threadIdx.x, wid = tid >> 5, lane = tid & 31;
    const int n0 = blockIdx.x * 128, m0 = blockIdx.y * 128;
    const int gate = n0 >> 8, ub = n0 & 255;
    const int mw = (wid >> 2) * 64, nw = (wid & 3) * 32;

    const __nv_bfloat16* Bsrc[3] = { g_Whi, g_Whi, g_Wlo };

    float d[4][4][4];
#pragma unroll
    for (int i = 0; i < 4; i++)
#pragma unroll
        for (int j = 0; j < 4; j++)
#pragma unroll
            for (int q = 0; q < 4; q++) d[i][j][q] = 0.f;

    uint4 ra[4], rb[4];
    const int lrow = tid >> 3, lj = tid & 7;

    auto ldg = [&](int c) {
        int sp = c >> 3, kc = (c & 7) << 6;
        const float* Ap = Ax + (size_t)m0 * 512 + kc;
        const __nv_bfloat16* Bp = Bsrc[sp] + (size_t)n0 * 512 + kc;
#pragma unroll
        for (int it = 0; it < 4; it++) {
            int row = lrow + 32 * it;
            const float* rp = Ap + (size_t)row * 512 + lj * 8;
            float4 f0 = *(const float4*)rp;
            float4 f1 = *(const float4*)(rp + 4);
            if (sp == 1) {
                ra[it] = make_uint4(bflo2(f0.x, f0.y), bflo2(f0.z, f0.w),
                                    bflo2(f1.x, f1.y), bflo2(f1.z, f1.w));
            } else {
                ra[it] = make_uint4(bfhi2(f0.x, f0.y), bfhi2(f0.z, f0.w),
                                    bfhi2(f1.x, f1.y), bfhi2(f1.z, f1.w));
            }
            rb[it] = *(const uint4*)(Bp + (size_t)row * 512 + lj * 8);
        }
    };
    auto sts = [&](int s) {
        char* at = sh + s * 32768;
        char* bt = at + 16384;
#pragma unroll
        for (int it = 0; it < 4; it++) {
            int row = lrow + 32 * it;
            uint32_t off = SWZ((uint32_t)(row * 128 + lj * 16));
            *(uint4*)(at + off) = ra[it];
            *(uint4*)(bt + off) = rb[it];
        }
    };

    ldg(0); sts(0);
    __syncthreads();

    for (int c = 0; c < 24; c++) {
        const int s = c & 1;
        if (c < 23) ldg(c + 1);
        const uint32_t sA = sb + s * 32768, sB = sA + 16384;
#pragma unroll
        for (int k16 = 0; k16 < 4; k16++) {
            const uint32_t colb = k16 * 32 + ((lane >> 4) << 4);
            uint32_t a[4][4], b[2][4];
#pragma unroll
            for (int im = 0; im < 4; im++) {
                int r = mw + im * 16 + (lane & 15);
                ldsm_x4(a[im][0], a[im][1], a[im][2], a[im][3],
                        sA + SWZ((uint32_t)(r * 128 + colb)));
            }
#pragma unroll
            for (int jn = 0; jn < 2; jn++) {
                int r = nw + jn * 16 + (lane & 15);
                ldsm_x4(b[jn][0], b[jn][1], b[jn][2], b[jn][3],
                        sB + SWZ((uint32_t)(r * 128 + colb)));
            }
#pragma unroll
            for (int im = 0; im < 4; im++)
#pragma unroll
                for (int j = 0; j < 4; j++)
                    mma16816(d[im][j], a[im], b[j >> 1][j & 1], b[j >> 1][2 + (j & 1)]);
        }
        if (c < 23) {
            sts(s ^ 1);
            __syncthreads();
        }
    }

#pragma unroll
    for (int j = 0; j < 4; j++) {
        int nl = nw + j * 8 + (lane & 3) * 2;
        int u = ub + nl;
        float bv0 = p.B[gate][u] + p.R[gate][u];
        float bv1 = p.B[gate][u + 1] + p.R[gate][u + 1];
#pragma unroll
        for (int im = 0; im < 4; im++) {
            int m = m0 + mw + im * 16 + (lane >> 2);
            float2 v0 = { d[im][j][0] + bv0, d[im][j][1] + bv1 };
            float2 v1 = { d[im][j][2] + bv0, d[im][j][3] + bv1 };
            *(float2*)(g_X + (size_t)m * 1024 + n0 + nl) = v0;
            *(float2*)(g_X + (size_t)(m + 8) * 1024 + n0 + nl) = v1;
        }
    }
}

// ---------------------------------------------------------------------------
// Kernel 2: persistent recurrence. Grid (16 unit-tiles, 8 batch-groups),
// 512 threads (16 warps, 4/SMSP). 4-way k-split across warp-quads with smem
// partial-sum reduction. Flag barrier, X prefetch, approx gates.
// ---------------------------------------------------------------------------
__global__ void __launch_bounds__(512, 1) rnn_kernel(P12 p, float* __restrict__ out,
                                                     int out_elems) {
    extern __shared__ char shm[];
    ulonglong2* WS2 = (ulonglong2*)shm;                  // [64 q][64 r] (r=g*16+u), 64KB
    ulonglong2* HS2 = (ulonglong2*)(shm + 65536);        // [32 b][65] padded, 33280B
    float* PS = (float*)(shm + 65536 + 33280);           // [4 kg][32 b][64 n], 32KB

    const int tid = threadIdx.x;
    const int tn = tid & 15, tm = tid >> 4;              // final mapping: tm 0..31
    const int w = tid >> 5, lane = tid & 31;
    const int kg = w >> 2;                               // k-group 0..3
    const int bloc = ((w & 3) << 1) | (lane >> 4);       // 0..7
    const int tn2 = lane & 15;
    const int u0 = blockIdx.x * 16, bb = blockIdx.y, b0 = bb * 32;
    const int unit = u0 + tn;
    const int myflag = bb * 16 + blockIdx.x;

    for (int idx = tid; idx < 4096; idx += 512) {
        int r = idx & 63, q = idx >> 6;
        int g = r >> 4, ui = r & 15;
        const float* wp = p.W[g] + (size_t)(u0 + ui) * 768 + 512 + 4 * q;
        WS2[idx] = make_ulonglong2(pk(wp[0], wp[1]), pk(wp[2], wp[3]));
    }
    __shared__ unsigned s_gen0;
    if (tid == 0) s_gen0 = g_flags[myflag * 32];
    __syncthreads();
    const unsigned gen0 = s_gen0;

    float c = 0.f;
    const size_t xoff = (size_t)(b0 + tm) * 1024 + unit;

    float xpre[4];
    {
        const float* Xn = g_X + xoff;
#pragma unroll
        for (int j = 0; j < 4; j++) xpre[j] = __ldcs(Xn + j * 256);
    }

    for (int t = 0; t < 512; t++) {
        if (t > 0) {
            const float4* hsrc = (const float4*)g_h[(t + 1) & 1];
#pragma unroll
            for (int i = 0; i < 4; i++) {
                int idx = tid + 512 * i;
                int bi = idx >> 6, q = idx & 63;
                float4 v = __ldcg(hsrc + (size_t)(b0 + bi) * 64 + q);
                HS2[bi * 65 + q] = make_ulonglong2(pk(v.x, v.y), pk(v.z, v.w));
            }
        }
        // prefetch X(t+1) — in flight during k-loop + barrier
        float xnext[4];
        if (t < 511) {
            const float* Xn = g_X + ((size_t)(t + 1) << 18) + xoff;
#pragma unroll
            for (int j = 0; j < 4; j++) xnext[j] = __ldcs(Xn + j * 256);
        }

        if (t > 0) {
            __syncthreads();
            ull acc[4][4];
#pragma unroll
            for (int i = 0; i < 4; i++)
#pragma unroll
                for (int g = 0; g < 4; g++) acc[i][g] = 0ull;
            const int qb = kg * 16;
#pragma unroll 4
            for (int q = qb; q < qb + 16; q++) {
                ulonglong2 a0 = HS2[bloc * 65 + q];
                ulonglong2 a1 = HS2[(bloc + 8) * 65 + q];
                ulonglong2 a2 = HS2[(bloc + 16) * 65 + q];
                ulonglong2 a3 = HS2[(bloc + 24) * 65 + q];
                ulonglong2 w0 = WS2[q * 64 + tn2];
                ulonglong2 w1 = WS2[q * 64 + tn2 + 16];
                ulonglong2 w2 = WS2[q * 64 + tn2 + 32];
                ulonglong2 w3 = WS2[q * 64 + tn2 + 48];
                fma2(acc[0][0], a0.x, w0.x); fma2(acc[0][0], a0.y, w0.y);
                fma2(acc[0][1], a0.x, w1.x); fma2(acc[0][1], a0.y, w1.y);
                fma2(acc[0][2], a0.x, w2.x); fma2(acc[0][2], a0.y, w2.y);
                fma2(acc[0][3], a0.x, w3.x); fma2(acc[0][3], a0.y, w3.y);
                fma2(acc[1][0], a1.x, w0.x); fma2(acc[1][0], a1.y, w0.y);
                fma2(acc[1][1], a1.x, w1.x); fma2(acc[1][1], a1.y, w1.y);
                fma2(acc[1][2], a1.x, w2.x); fma2(acc[1][2], a1.y, w2.y);
                fma2(acc[1][3], a1.x, w3.x); fma2(acc[1][3], a1.y, w3.y);
                fma2(acc[2][0], a2.x, w0.x); fma2(acc[2][0], a2.y, w0.y);
                fma2(acc[2][1], a2.x, w1.x); fma2(acc[2][1], a2.y, w1.y);
                fma2(acc[2][2], a2.x, w2.x); fma2(acc[2][2], a2.y, w2.y);
                fma2(acc[2][3], a2.x, w3.x); fma2(acc[2][3], a2.y, w3.y);
                fma2(acc[3][0], a3.x, w0.x); fma2(acc[3][0], a3.y, w0.y);
                fma2(acc[3][1], a3.x, w1.x); fma2(acc[3][1], a3.y, w1.y);
                fma2(acc[3][2], a3.x, w2.x); fma2(acc[3][2], a3.y, w2.y);
                fma2(acc[3][3], a3.x, w3.x); fma2(acc[3][3], a3.y, w3.y);
            }
            float* PSk = PS + kg * 2048;
#pragma unroll
            for (int i = 0; i < 4; i++)
#pragma unroll
                for (int g = 0; g < 4; g++)
                    PSk[(bloc + 8 * i) * 64 + g * 16 + tn2] = lane_sum(acc[i][g]);
            __syncthreads();
        }

        // final: sum partials + X, gates, c/h update
        float S[4];
#pragma unroll
        for (int g = 0; g < 4; g++) S[g] = xpre[g];
        if (t > 0) {
            const float* Pb = PS + tm * 64 + tn;
#pragma unroll
            for (int g = 0; g < 4; g++)
#pragma unroll
                for (int k2 = 0; k2 < 4; k2++)
                    S[g] += Pb[k2 * 2048 + g * 16];
        }
        float pf = sigm_fast(S[0]);
        float pi = sigm_fast(S[1]);
        float pu = sigm_fast(S[2]);
        float po = sigm_fast(S[3]);
        c = pf * c + pi * pu;
        float h = po * tanh_fast(c);
        g_h[t & 1][(b0 + tm) * 256 + unit] = h;
#pragma unroll
        for (int j = 0; j < 4; j++) xpre[j] = xnext[j];

        if (t < 511) {
            __syncthreads();                      // all h stores issued
            if (tid == 0)
                st_release(&g_flags[myflag * 32], gen0 + (unsigned)t + 1u);
            out[(size_t)t * 65536 + (b0 + tm) * 256 + unit] = h;   // overlaps barrier
            if (tid < 16) {
                const unsigned* fp = &g_flags[(bb * 16 + tid) * 32];
                unsigned want = gen0 + (unsigned)t + 1u;
                while ((int)(ld_acquire(fp) - want) < 0) { }
            }
            __syncthreads();
        } else {
            int b = b0 + tm;
            out[(size_t)t * 65536 + b * 256 + unit] = h;
            if (out_elems >= 33685504) {
                out[33554432 + b * 256 + unit] = h;   // hx
                out[33619968 + b * 256 + unit] = c;   // cx
            }
        }
    }
}

// ---------------------------------------------------------------------------
extern "C" void kernel_launch(void* const* d_in, const int* in_sizes, int n_in,
                              void* d_out, int out_size) {
    const float* x = (const float*)d_in[0];
    P12 p;
    if (n_in >= 13 && in_sizes[3] == 196608) {
        for (int g = 0; g < 4; g++) {
            p.W[g] = (const float*)d_in[1 + 2 * g];
            p.B[g] = (const float*)d_in[2 + 2 * g];
            p.R[g] = (const float*)d_in[9 + g];
        }
    } else {
        for (int g = 0; g < 4; g++) {
            p.W[g] = (const float*)d_in[1 + 3 * g];
            p.B[g] = (const float*)d_in[2 + 3 * g];
            p.R[g] = (const float*)d_in[3 + 3 * g];
        }
    }

    cvtW_kernel<<<2048, 256>>>(p);

    cudaFuncSetAttribute(g1mma_kernel, cudaFuncAttributeMaxDynamicSharedMemorySize, 65536);
    g1mma_kernel<<<dim3(8, 1024), 256, 65536>>>(x, p);

    cudaFuncSetAttribute(rnn_kernel, cudaFuncAttributeMaxDynamicSharedMemorySize, 131584);
    rnn_kernel<<<dim3(16, 8), 512, 131584>>>(p, (float*)d_out, out_size);
}

// round 9
// speedup vs baseline: 2.1750x; 1.3230x over previous
#include <cuda_runtime.h>
#include <cuda_bf16.h>
#include <cstdint>

struct P12 { const float* W[4]; const float* B[4]; const float* R[4]; };

// ---------------- persistent device scratch (no allocations allowed) --------
__device__ float g_X[(size_t)512 * 256 * 1024];   // pre-activations [t][b][g*256+u]
__device__ __nv_bfloat16 g_hH[2][256 * 256];      // h hi, ping-pong
__device__ __nv_bfloat16 g_hL[2][256 * 256];      // h lo
__device__ unsigned g_flags[128 * 32];            // per-CTA barrier flags (128B apart)
__device__ __nv_bfloat16 g_Whi[1024 * 512];       // W (input cols) hi
__device__ __nv_bfloat16 g_Wlo[1024 * 512];

// ---------------- helpers ----------------------------------------------------
__device__ __forceinline__ float ex2a(float x) {
    float r; asm("ex2.approx.f32 %0, %1;" : "=f"(r) : "f"(x)); return r;
}
__device__ __forceinline__ float rcpa(float x) {
    float r; asm("rcp.approx.f32 %0, %1;" : "=f"(r) : "f"(x)); return r;
}
__device__ __forceinline__ float sigm_fast(float x) {
    return rcpa(1.0f + ex2a(-1.4426950408889634f * x));
}
__device__ __forceinline__ float tanh_fast(float x) {
    return 1.0f - 2.0f * rcpa(1.0f + ex2a(2.8853900817779268f * x));
}
__device__ __forceinline__ uint32_t smem_u32(const void* p) {
    uint32_t a; asm("{ .reg .u64 t; cvta.to.shared.u64 t, %1; cvt.u32.u64 %0, t; }"
                    : "=r"(a) : "l"(p)); return a;
}
__device__ __forceinline__ void st_release(unsigned* p, unsigned v) {
    asm volatile("st.release.gpu.u32 [%0], %1;" :: "l"(p), "r"(v) : "memory");
}
__device__ __forceinline__ unsigned ld_acquire(const unsigned* p) {
    unsigned v; asm volatile("ld.acquire.gpu.u32 %0, [%1];" : "=r"(v) : "l"(p) : "memory");
    return v;
}
__device__ __forceinline__ uint32_t bfhi2(float a, float b) {
    __nv_bfloat162 h = __float22bfloat162_rn(make_float2(a, b));
    return *reinterpret_cast<uint32_t*>(&h);
}
__device__ __forceinline__ uint32_t bflo2(float a, float b) {
    __nv_bfloat162 h = __float22bfloat162_rn(make_float2(a, b));
    float2 hf = __bfloat1622float2(h);
    __nv_bfloat162 l = __float22bfloat162_rn(make_float2(a - hf.x, b - hf.y));
    return *reinterpret_cast<uint32_t*>(&l);
}
#define SWZ(x) ((x) ^ (((x) >> 3) & 0x70))

__device__ __forceinline__ void ldsm_x4(uint32_t& r0, uint32_t& r1, uint32_t& r2,
                                        uint32_t& r3, uint32_t addr) {
    asm volatile("ldmatrix.sync.aligned.m8n8.x4.shared.b16 {%0,%1,%2,%3}, [%4];"
                 : "=r"(r0), "=r"(r1), "=r"(r2), "=r"(r3) : "r"(addr));
}
__device__ __forceinline__ void mma16816(float* d, const uint32_t* a,
                                         uint32_t b0, uint32_t b1) {
    asm volatile("mma.sync.aligned.m16n8k16.row.col.f32.bf16.bf16.f32 "
                 "{%0,%1,%2,%3}, {%4,%5,%6,%7}, {%8,%9}, {%0,%1,%2,%3};"
                 : "+f"(d[0]), "+f"(d[1]), "+f"(d[2]), "+f"(d[3])
                 : "r"(a[0]), "r"(a[1]), "r"(a[2]), "r"(a[3]), "r"(b0), "r"(b1));
}

// ---------------------------------------------------------------------------
// W conversion (input cols 0..511 only): fp32 -> bf16 hi/lo split
// ---------------------------------------------------------------------------
__global__ void cvtW_kernel(P12 p) {
    int i = blockIdx.x * blockDim.x + threadIdx.x;
    if (i >= 1024 * 512) return;
    int nrow = i >> 9, k = i & 511;
    int g = nrow >> 8, u = nrow & 255;
    float v = p.W[g][(size_t)u * 768 + k];
    __nv_bfloat16 h = __float2bfloat16(v);
    g_Whi[i] = h;
    g_Wlo[i] = __float2bfloat16(v - __bfloat162float(h));
}

// ---------------------------------------------------------------------------
// Kernel 1 (mma.sync bf16): X[m][n] = x[m] . W[n] + (b+r)[n]  (unchanged)
// ---------------------------------------------------------------------------
__global__ void __launch_bounds__(256, 1) g1mma_kernel(const float* __restrict__ Ax, P12 p) {
    extern __shared__ __align__(1024) char sh[];
    uint32_t sb = smem_u32(sh);
    const int tid = threadIdx.x, wid = tid >> 5, lane = tid & 31;
    const int n0 = blockIdx.x * 128, m0 = blockIdx.y * 128;
    const int gate = n0 >> 8, ub = n0 & 255;
    const int mw = (wid >> 2) * 64, nw = (wid & 3) * 32;

    const __nv_bfloat16* Bsrc[3] = { g_Whi, g_Whi, g_Wlo };

    float d[4][4][4];
#pragma unroll
    for (int i = 0; i < 4; i++)
#pragma unroll
        for (int j = 0; j < 4; j++)
#pragma unroll
            for (int q = 0; q < 4; q++) d[i][j][q] = 0.f;

    uint4 ra[4], rb[4];
    const int lrow = tid >> 3, lj = tid & 7;

    auto ldg = [&](int c) {
        int sp = c >> 3, kc = (c & 7) << 6;
        const float* Ap = Ax + (size_t)m0 * 512 + kc;
        const __nv_bfloat16* Bp = Bsrc[sp] + (size_t)n0 * 512 + kc;
#pragma unroll
        for (int it = 0; it < 4; it++) {
            int row = lrow + 32 * it;
            const float* rp = Ap + (size_t)row * 512 + lj * 8;
            float4 f0 = *(const float4*)rp;
            float4 f1 = *(const float4*)(rp + 4);
            if (sp == 1) {
                ra[it] = make_uint4(bflo2(f0.x, f0.y), bflo2(f0.z, f0.w),
                                    bflo2(f1.x, f1.y), bflo2(f1.z, f1.w));
            } else {
                ra[it] = make_uint4(bfhi2(f0.x, f0.y), bfhi2(f0.z, f0.w),
                                    bfhi2(f1.x, f1.y), bfhi2(f1.z, f1.w));
            }
            rb[it] = *(const uint4*)(Bp + (size_t)row * 512 + lj * 8);
        }
    };
    auto sts = [&](int s) {
        char* at = sh + s * 32768;
        char* bt = at + 16384;
#pragma unroll
        for (int it = 0; it < 4; it++) {
            int row = lrow + 32 * it;
            uint32_t off = SWZ((uint32_t)(row * 128 + lj * 16));
            *(uint4*)(at + off) = ra[it];
            *(uint4*)(bt + off) = rb[it];
        }
    };

    ldg(0); sts(0);
    __syncthreads();

    for (int c = 0; c < 24; c++) {
        const int s = c & 1;
        if (c < 23) ldg(c + 1);
        const uint32_t sA = sb + s * 32768, sB = sA + 16384;
#pragma unroll
        for (int k16 = 0; k16 < 4; k16++) {
            const uint32_t colb = k16 * 32 + ((lane >> 4) << 4);
            uint32_t a[4][4], b[2][4];
#pragma unroll
            for (int im = 0; im < 4; im++) {
                int r = mw + im * 16 + (lane & 15);
                ldsm_x4(a[im][0], a[im][1], a[im][2], a[im][3],
                        sA + SWZ((uint32_t)(r * 128 + colb)));
            }
#pragma unroll
            for (int jn = 0; jn < 2; jn++) {
                int r = nw + jn * 16 + (lane & 15);
                ldsm_x4(b[jn][0], b[jn][1], b[jn][2], b[jn][3],
                        sB + SWZ((uint32_t)(r * 128 + colb)));
            }
#pragma unroll
            for (int im = 0; im < 4; im++)
#pragma unroll
                for (int j = 0; j < 4; j++)
                    mma16816(d[im][j], a[im], b[j >> 1][j & 1], b[j >> 1][2 + (j & 1)]);
        }
        if (c < 23) {
            sts(s ^ 1);
            __syncthreads();
        }
    }

#pragma unroll
    for (int j = 0; j < 4; j++) {
        int nl = nw + j * 8 + (lane & 3) * 2;
        int u = ub + nl;
        float bv0 = p.B[gate][u] + p.R[gate][u];
        float bv1 = p.B[gate][u + 1] + p.R[gate][u + 1];
#pragma unroll
        for (int im = 0; im < 4; im++) {
            int m = m0 + mw + im * 16 + (lane >> 2);
            float2 v0 = { d[im][j][0] + bv0, d[im][j][1] + bv1 };
            float2 v1 = { d[im][j][2] + bv0, d[im][j][3] + bv1 };
            *(float2*)(g_X + (size_t)m * 1024 + n0 + nl) = v0;
            *(float2*)(g_X + (size_t)(m + 8) * 1024 + n0 + nl) = v1;
        }
    }
}

// ---------------------------------------------------------------------------
// Kernel 2: persistent recurrence, tensorized.
// Grid (16 unit-tiles, 8 batch-groups), 512 threads = 16 warps.
// Warp (kg, mt, nt): k-slice 64 (kg), m16 batches (mt), n32 outputs (nt).
// Wh fragments (bf16 hi/lo) live in REGISTERS for all 512 steps.
// Per step: h (bf16 hi/lo) global->smem, ldsm A frags, 48 mma, PS reduce,
// gates in fp32, h re-split to bf16 hi/lo. Flag barrier per step.
// SMEM: HHI[32][264]bf16 @0 (16896B), HLO @16896, PS[4][32][64]f32 @33792.
// Init: W staged at @0 (64x264 bf16 = 33792B), then overwritten by HHI/HLO.
// ---------------------------------------------------------------------------
__global__ void __launch_bounds__(512, 1) rnn_mma_kernel(P12 p, float* __restrict__ out,
                                                         int out_elems) {
    extern __shared__ __align__(16) char shm[];
    float* PS = (float*)(shm + 33792);
    const uint32_t sb = smem_u32(shm);

    const int tid = threadIdx.x, w = tid >> 5, lane = tid & 31;
    const int kg = w & 3, mt = (w >> 2) & 1, nt = (w >> 3) & 1;
    const int b = tid >> 4, u = tid & 15;           // gate-phase mapping
    const int u0 = blockIdx.x * 16, bb = blockIdx.y, b0 = bb * 32;
    const int myflag = bb * 16 + blockIdx.x;

    // ---- init: stage Wh (hidden cols 512..767) as bf16, ldsm frags to regs
    uint32_t wH[2][4][4], wL[2][4][4];
    {
        __nv_bfloat16* Wtmp = (__nv_bfloat16*)shm;   // [64 n][264] (528B rows)
        // pass 0: hi
        for (int idx = tid; idx < 64 * 256; idx += 512) {
            int r = idx >> 8, k = idx & 255;
            int g = r >> 4, ui = r & 15;
            float v = p.W[g][(size_t)(u0 + ui) * 768 + 512 + k];
            Wtmp[r * 264 + k] = __float2bfloat16(v);
        }
        __syncthreads();
#pragma unroll
        for (int jn2 = 0; jn2 < 2; jn2++)
#pragma unroll
            for (int kb = 0; kb < 4; kb++) {
                uint32_t a = sb + (uint32_t)((nt * 32 + jn2 * 16 + (lane & 15)) * 528
                                             + kg * 128 + kb * 32 + ((lane >> 4) << 4));
                ldsm_x4(wH[jn2][kb][0], wH[jn2][kb][1], wH[jn2][kb][2], wH[jn2][kb][3], a);
            }
        __syncthreads();
        // pass 1: lo
        for (int idx = tid; idx < 64 * 256; idx += 512) {
            int r = idx >> 8, k = idx & 255;
            int g = r >> 4, ui = r & 15;
            float v = p.W[g][(size_t)(u0 + ui) * 768 + 512 + k];
            __nv_bfloat16 hb = __float2bfloat16(v);
            Wtmp[r * 264 + k] = __float2bfloat16(v - __bfloat162float(hb));
        }
        __syncthreads();
#pragma unroll
        for (int jn2 = 0; jn2 < 2; jn2++)
#pragma unroll
            for (int kb = 0; kb < 4; kb++) {
                uint32_t a = sb + (uint32_t)((nt * 32 + jn2 * 16 + (lane & 15)) * 528
                                             + kg * 128 + kb * 32 + ((lane >> 4) << 4));
                ldsm_x4(wL[jn2][kb][0], wL[jn2][kb][1], wL[jn2][kb][2], wL[jn2][kb][3], a);
            }
        __syncthreads();
    }

    __shared__ unsigned s_gen0;
    if (tid == 0) s_gen0 = g_flags[myflag * 32];
    __syncthreads();
    const unsigned gen0 = s_gen0;

    float c = 0.f;
    const size_t xoff = (size_t)(b0 + b) * 1024 + u0 + u;

    float xpre[4];
    {
        const float* Xn = g_X + xoff;
#pragma unroll
        for (int g = 0; g < 4; g++) xpre[g] = __ldcs(Xn + g * 256);
    }

    for (int t = 0; t < 512; t++) {
        // fill h smem (bf16 hi/lo) from previous step
        if (t > 0) {
            const uint4* srcH = (const uint4*)(g_hH[(t + 1) & 1]);  // == (t-1)&1
            const uint4* srcL = (const uint4*)(g_hL[(t + 1) & 1]);
#pragma unroll
            for (int i = 0; i < 2; i++) {
                int idx = tid + 512 * i;
                int row = idx >> 5, c8 = idx & 31;
                uint4 vh = __ldcg(srcH + (size_t)(b0 + row) * 32 + c8);
                uint4 vl = __ldcg(srcL + (size_t)(b0 + row) * 32 + c8);
                *(uint4*)(shm + row * 528 + c8 * 16) = vh;
                *(uint4*)(shm + 16896 + row * 528 + c8 * 16) = vl;
            }
        }
        // prefetch X(t+1)
        float xnext[4];
        if (t < 511) {
            const float* Xn = g_X + ((size_t)(t + 1) << 18) + xoff;
#pragma unroll
            for (int g = 0; g < 4; g++) xnext[g] = __ldcs(Xn + g * 256);
        }

        if (t > 0) {
            __syncthreads();
            float d[4][4];
#pragma unroll
            for (int j = 0; j < 4; j++)
#pragma unroll
                for (int q = 0; q < 4; q++) d[j][q] = 0.f;

#pragma unroll
            for (int kb = 0; kb < 4; kb++) {
                uint32_t aH[4], aL[4];
                uint32_t ar = sb + (uint32_t)((mt * 16 + (lane & 15)) * 528
                                              + kg * 128 + kb * 32 + ((lane >> 4) << 4));
                ldsm_x4(aH[0], aH[1], aH[2], aH[3], ar);
                ldsm_x4(aL[0], aL[1], aL[2], aL[3], ar + 16896u);
#pragma unroll
                for (int j = 0; j < 4; j++) {
                    mma16816(d[j], aH, wH[j >> 1][kb][j & 1], wH[j >> 1][kb][2 + (j & 1)]);
                    mma16816(d[j], aL, wH[j >> 1][kb][j & 1], wH[j >> 1][kb][2 + (j & 1)]);
                    mma16816(d[j], aH, wL[j >> 1][kb][j & 1], wL[j >> 1][kb][2 + (j & 1)]);
                }
            }
            // scatter partials to PS with rotate-by-4b swizzle
#pragma unroll
            for (int j = 0; j < 4; j++) {
                int bl = mt * 16 + (lane >> 2);
                int n = nt * 32 + j * 8 + (lane & 3) * 2;
                int c0 = (n + 4 * bl) & 63;
                *(float2*)(PS + kg * 2048 + bl * 64 + c0) = make_float2(d[j][0], d[j][1]);
                int bl2 = bl + 8;
                int c2 = (n + 4 * bl2) & 63;
                *(float2*)(PS + kg * 2048 + bl2 * 64 + c2) = make_float2(d[j][2], d[j][3]);
            }
            __syncthreads();
        }

        // reduce partials + X, gates, c/h update
        float S[4];
#pragma unroll
        for (int g = 0; g < 4; g++) S[g] = xpre[g];
        if (t > 0) {
#pragma unroll
            for (int g = 0; g < 4; g++) {
                int cc = (g * 16 + u + 4 * b) & 63;
#pragma unroll
                for (int k2 = 0; k2 < 4; k2++)
                    S[g] += PS[k2 * 2048 + b * 64 + cc];
            }
        }
        float pf = sigm_fast(S[0]);
        float pi = sigm_fast(S[1]);
        float pu = sigm_fast(S[2]);
        float po = sigm_fast(S[3]);
        c = pf * c + pi * pu;
        float h = po * tanh_fast(c);

        // store h as bf16 hi/lo for the next step's matmul
        __nv_bfloat16 hh = __float2bfloat16(h);
        __nv_bfloat16 hl = __float2bfloat16(h - __bfloat162float(hh));
        size_t hidx = (size_t)(b0 + b) * 256 + u0 + u;
        g_hH[t & 1][hidx] = hh;
        g_hL[t & 1][hidx] = hl;

#pragma unroll
        for (int g = 0; g < 4; g++) xpre[g] = xnext[g];

        if (t < 511) {
            __syncthreads();                      // all h stores issued CTA-wide
            if (tid == 0)
                st_release(&g_flags[myflag * 32], gen0 + (unsigned)t + 1u);
            out[(size_t)t * 65536 + (b0 + b) * 256 + u0 + u] = h;  // overlaps barrier
            if (tid < 16) {
                const unsigned* fp = &g_flags[(bb * 16 + tid) * 32];
                unsigned want = gen0 + (unsigned)t + 1u;
                while ((int)(ld_acquire(fp) - want) < 0) { }
            }
            __syncthreads();
        } else {
            int gb = b0 + b;
            out[(size_t)t * 65536 + gb * 256 + u0 + u] = h;
            if (out_elems >= 33685504) {
                out[33554432 + gb * 256 + u0 + u] = h;   // hx
                out[33619968 + gb * 256 + u0 + u] = c;   // cx
            }
        }
    }
}

// ---------------------------------------------------------------------------
extern "C" void kernel_launch(void* const* d_in, const int* in_sizes, int n_in,
                              void* d_out, int out_size) {
    const float* x = (const float*)d_in[0];
    P12 p;
    if (n_in >= 13 && in_sizes[3] == 196608) {
        for (int g = 0; g < 4; g++) {
            p.W[g] = (const float*)d_in[1 + 2 * g];
            p.B[g] = (const float*)d_in[2 + 2 * g];
            p.R[g] = (const float*)d_in[9 + g];
        }
    } else {
        for (int g = 0; g < 4; g++) {
            p.W[g] = (const float*)d_in[1 + 3 * g];
            p.B[g] = (const float*)d_in[2 + 3 * g];
            p.R[g] = (const float*)d_in[3 + 3 * g];
        }
    }

    cvtW_kernel<<<2048, 256>>>(p);

    cudaFuncSetAttribute(g1mma_kernel, cudaFuncAttributeMaxDynamicSharedMemorySize, 65536);
    g1mma_kernel<<<dim3(8, 1024), 256, 65536>>>(x, p);

    cudaFuncSetAttribute(rnn_mma_kernel, cudaFuncAttributeMaxDynamicSharedMemorySize, 66560);
    rnn_mma_kernel<<<dim3(16, 8), 512, 66560>>>(p, (float*)d_out, out_size);
}

// round 11
// speedup vs baseline: 2.3291x; 1.0709x over previous
#include <cuda_runtime.h>
#include <cuda_bf16.h>
#include <cstdint>

struct P12 { const float* W[4]; const float* B[4]; const float* R[4]; };

// ---------------- persistent device scratch (no allocations allowed) --------
__device__ float g_X[(size_t)512 * 256 * 1024];   // pre-activations [t][b][g*256+u]
__device__ __nv_bfloat16 g_hH[2][256 * 256];      // h hi, ping-pong
__device__ __nv_bfloat16 g_hL[2][256 * 256];      // h lo
__device__ unsigned g_flags[128 * 32];            // per-CTA barrier flags (128B apart)
__device__ __nv_bfloat16 g_Ahi[(size_t)131072 * 512];
__device__ __nv_bfloat16 g_Alo[(size_t)131072 * 512];
__device__ __nv_bfloat16 g_Whi[1024 * 512];       // W (input cols) hi
__device__ __nv_bfloat16 g_Wlo[1024 * 512];

// ---------------- helpers ----------------------------------------------------
__device__ __forceinline__ float ex2a(float x) {
    float r; asm("ex2.approx.f32 %0, %1;" : "=f"(r) : "f"(x)); return r;
}
__device__ __forceinline__ float rcpa(float x) {
    float r; asm("rcp.approx.f32 %0, %1;" : "=f"(r) : "f"(x)); return r;
}
__device__ __forceinline__ float sigm_fast(float x) {
    return rcpa(1.0f + ex2a(-1.4426950408889634f * x));
}
__device__ __forceinline__ float tanh_fast(float x) {
    return 1.0f - 2.0f * rcpa(1.0f + ex2a(2.8853900817779268f * x));
}
__device__ __forceinline__ uint32_t smem_u32(const void* p) {
    uint32_t a; asm("{ .reg .u64 t; cvta.to.shared.u64 t, %1; cvt.u32.u64 %0, t; }"
                    : "=r"(a) : "l"(p)); return a;
}
__device__ __forceinline__ void st_release(unsigned* p, unsigned v) {
    asm volatile("st.release.gpu.u32 [%0], %1;" :: "l"(p), "r"(v) : "memory");
}
__device__ __forceinline__ unsigned ld_acquire(const unsigned* p) {
    unsigned v; asm volatile("ld.acquire.gpu.u32 %0, [%1];" : "=r"(v) : "l"(p) : "memory");
    return v;
}
__device__ __forceinline__ void cpa16(uint32_t smem, const void* g) {
    asm volatile("cp.async.cg.shared.global [%0], [%1], 16;" :: "r"(smem), "l"(g));
}
#define CP_COMMIT() asm volatile("cp.async.commit_group;" ::: "memory")
#define CP_WAIT(n)  asm volatile("cp.async.wait_group %0;" :: "n"(n) : "memory")
#define SWZ(x) ((x) ^ (((x) >> 3) & 0x70))

__device__ __forceinline__ void ldsm_x4(uint32_t& r0, uint32_t& r1, uint32_t& r2,
                                        uint32_t& r3, uint32_t addr) {
    asm volatile("ldmatrix.sync.aligned.m8n8.x4.shared.b16 {%0,%1,%2,%3}, [%4];"
                 : "=r"(r0), "=r"(r1), "=r"(r2), "=r"(r3) : "r"(addr));
}
__device__ __forceinline__ void mma16816(float* d, const uint32_t* a,
                                         uint32_t b0, uint32_t b1) {
    asm volatile("mma.sync.aligned.m16n8k16.row.col.f32.bf16.bf16.f32 "
                 "{%0,%1,%2,%3}, {%4,%5,%6,%7}, {%8,%9}, {%0,%1,%2,%3};"
                 : "+f"(d[0]), "+f"(d[1]), "+f"(d[2]), "+f"(d[3])
                 : "r"(a[0]), "r"(a[1]), "r"(a[2]), "r"(a[3]), "r"(b0), "r"(b1));
}

// ---------------------------------------------------------------------------
// Conversions: fp32 -> bf16 hi/lo
// ---------------------------------------------------------------------------
__global__ void cvtA_kernel(const float* __restrict__ A) {
    size_t i = (size_t)blockIdx.x * blockDim.x + threadIdx.x;
    size_t n = (size_t)131072 * 512;
    for (; i < n; i += (size_t)gridDim.x * blockDim.x) {
        float v = A[i];
        __nv_bfloat16 h = __float2bfloat16(v);
        g_Ahi[i] = h;
        g_Alo[i] = __float2bfloat16(v - __bfloat162float(h));
    }
}
__global__ void cvtW_kernel(P12 p) {
    int i = blockIdx.x * blockDim.x + threadIdx.x;
    if (i >= 1024 * 512) return;
    int nrow = i >> 9, k = i & 511;
    int g = nrow >> 8, u = nrow & 255;
    float v = p.W[g][(size_t)u * 768 + k];
    __nv_bfloat16 h = __float2bfloat16(v);
    g_Whi[i] = h;
    g_Wlo[i] = __float2bfloat16(v - __bfloat162float(h));
}

// ---------------------------------------------------------------------------
// Kernel 1: X[m][n] = x[m].W[n] + (b+r)[n]
//   CTA 128m x 256n (one gate), grid (4,1024). cp.async 4-stage pipeline,
//   8 warps with 64x64 tiles, 24 chunks (3 bf16-split passes x K=512).
//   Stage: A 128x128B (16KB) + B 256x128B (32KB) = 48KB; 4 stages = 192KB.
//   Fill budget: 12 x 16B cp.async per thread per stage (A:4, B:8).
// ---------------------------------------------------------------------------
__global__ void __launch_bounds__(256, 1) g1mma_kernel(P12 p) {
    extern __shared__ __align__(1024) char sh[];
    uint32_t sb = smem_u32(sh);
    const int tid = threadIdx.x, wid = tid >> 5, lane = tid & 31;
    const int gate = blockIdx.x, n0 = gate * 256;
    const int m0 = blockIdx.y * 128;
    const int mw = (wid >> 2) * 64, nw = (wid & 3) * 64;

    const __nv_bfloat16* Asrc[3] = { g_Ahi, g_Alo, g_Ahi };
    const __nv_bfloat16* Bsrc[3] = { g_Whi, g_Whi, g_Wlo };

    float d[4][8][4];
#pragma unroll
    for (int i = 0; i < 4; i++)
#pragma unroll
        for (int j = 0; j < 8; j++)
#pragma unroll
            for (int q = 0; q < 4; q++) d[i][j][q] = 0.f;

    const int arow = tid >> 1, asl = (tid & 1) * 4;   // A: 2 threads/row, 4 slots each

    auto stage_fill = [&](int c, int s) {
        int sp = c >> 3, kc = (c & 7) << 6;
        const __nv_bfloat16* Ap = Asrc[sp] + (size_t)(m0 + arow) * 512 + kc;
        uint32_t ab = sb + s * 49152;
#pragma unroll
        for (int j = 0; j < 4; j++)
            cpa16(ab + SWZ((uint32_t)(arow * 128 + (asl + j) * 16)), Ap + (asl + j) * 8);
        const __nv_bfloat16* Bp = Bsrc[sp] + (size_t)(n0 + tid) * 512 + kc;
        uint32_t bb = ab + 16384;
#pragma unroll
        for (int j = 0; j < 8; j++)
            cpa16(bb + SWZ((uint32_t)(tid * 128 + j * 16)), Bp + j * 8);
    };

#pragma unroll
    for (int s = 0; s < 3; s++) { stage_fill(s, s); CP_COMMIT(); }

    for (int c = 0; c < 24; c++) {
        CP_WAIT(2);
        __syncthreads();
        if (c + 3 < 24) stage_fill(c + 3, (c + 3) & 3);
        CP_COMMIT();

        const uint32_t sA = sb + (c & 3) * 49152, sB = sA + 16384;
#pragma unroll
        for (int k16 = 0; k16 < 4; k16++) {
            const uint32_t colb = k16 * 32 + ((lane >> 4) << 4);
            uint32_t a[4][4], b[4][4];
#pragma unroll
            for (int im = 0; im < 4; im++) {
                int r = mw + im * 16 + (lane & 15);
                ldsm_x4(a[im][0], a[im][1], a[im][2], a[im][3],
                        sA + SWZ((uint32_t)(r * 128 + colb)));
            }
#pragma unroll
            for (int jn = 0; jn < 4; jn++) {
                int r = nw + jn * 16 + (lane & 15);
                ldsm_x4(b[jn][0], b[jn][1], b[jn][2], b[jn][3],
                        sB + SWZ((uint32_t)(r * 128 + colb)));
            }
#pragma unroll
            for (int im = 0; im < 4; im++)
#pragma unroll
                for (int j = 0; j < 8; j++)
                    mma16816(d[im][j], a[im], b[j >> 1][j & 1], b[j >> 1][2 + (j & 1)]);
        }
    }

    // epilogue: registers -> g_X with bias+rot
#pragma unroll
    for (int j = 0; j < 8; j++) {
        int nl = nw + j * 8 + (lane & 3) * 2;
        float bv0 = p.B[gate][nl] + p.R[gate][nl];
        float bv1 = p.B[gate][nl + 1] + p.R[gate][nl + 1];
#pragma unroll
        for (int im = 0; im < 4; im++) {
            int m = m0 + mw + im * 16 + (lane >> 2);
            float2 v0 = { d[im][j][0] + bv0, d[im][j][1] + bv1 };
            float2 v1 = { d[im][j][2] + bv0, d[im][j][3] + bv1 };
            *(float2*)(g_X + (size_t)m * 1024 + n0 + nl) = v0;
            *(float2*)(g_X + (size_t)(m + 8) * 1024 + n0 + nl) = v1;
        }
    }
}

// ---------------------------------------------------------------------------
// Kernel 2: persistent recurrence, tensorized. Grid (8 unit-tiles, 16 batch-
// groups), 512 threads = 16 warps (kg 0..3 x nt 0..3, m16 = 16 batches).
// CTA: 32 units x 4 gates (128 n) x 16 batches. Wh frags in registers.
// Group = 8 CTAs sharing a batch slice; flag barrier per step.
// SMEM: HHI[16][264]bf16 @0 (8448B), HLO @8448, PS[4][16][128]f32 @16896.
// Init stages W as [128 n][264] bf16 (67584B) then reuses region.
// ---------------------------------------------------------------------------
__global__ void __launch_bounds__(512, 1) rnn_mma_kernel(P12 p, float* __restrict__ out,
                                                         int out_elems) {
    extern __shared__ __align__(16) char shm[];
    float* PS = (float*)(shm + 16896);
    const uint32_t sb = smem_u32(shm);

    const int tid = threadIdx.x, w = tid >> 5, lane = tid & 31;
    const int kg = w & 3, nt = w >> 2;               // kg 0..3, nt 0..3
    const int b = tid >> 5, u = tid & 31;            // gate-phase: batch=warp, unit=lane
    const int u0 = blockIdx.x * 32, by = blockIdx.y, b0 = by * 16;
    const int myflag = by * 8 + blockIdx.x;

    // ---- init: stage Wh (hidden cols) as bf16, ldsm frags to registers
    uint32_t wH[2][4][4], wL[2][4][4];
    {
        __nv_bfloat16* Wtmp = (__nv_bfloat16*)shm;   // [128 n][264]
        for (int idx = tid; idx < 128 * 256; idx += 512) {
            int r = idx >> 8, k = idx & 255;
            int g = r >> 5, ui = r & 31;
            float v = p.W[g][(size_t)(u0 + ui) * 768 + 512 + k];
            Wtmp[r * 264 + k] = __float2bfloat16(v);
        }
        __syncthreads();
#pragma unroll
        for (int jn2 = 0; jn2 < 2; jn2++)
#pragma unroll
            for (int kb = 0; kb < 4; kb++) {
                uint32_t a = sb + (uint32_t)((nt * 32 + jn2 * 16 + (lane & 15)) * 528
                                             + kg * 128 + kb * 32 + ((lane >> 4) << 4));
                ldsm_x4(wH[jn2][kb][0], wH[jn2][kb][1], wH[jn2][kb][2], wH[jn2][kb][3], a);
            }
        __syncthreads();
        for (int idx = tid; idx < 128 * 256; idx += 512) {
            int r = idx >> 8, k = idx & 255;
            int g = r >> 5, ui = r & 31;
            float v = p.W[g][(size_t)(u0 + ui) * 768 + 512 + k];
            __nv_bfloat16 hb = __float2bfloat16(v);
            Wtmp[r * 264 + k] = __float2bfloat16(v - __bfloat162float(hb));
        }
        __syncthreads();
#pragma unroll
        for (int jn2 = 0; jn2 < 2; jn2++)
#pragma unroll
            for (int kb = 0; kb < 4; kb++) {
                uint32_t a = sb + (uint32_t)((nt * 32 + jn2 * 16 + (lane & 15)) * 528
                                             + kg * 128 + kb * 32 + ((lane >> 4) << 4));
                ldsm_x4(wL[jn2][kb][0], wL[jn2][kb][1], wL[jn2][kb][2], wL[jn2][kb][3], a);
            }
        __syncthreads();
    }

    __shared__ unsigned s_gen0;
    if (tid == 0) s_gen0 = g_flags[myflag * 32];
    __syncthreads();
    const unsigned gen0 = s_gen0;

    float c = 0.f;
    const size_t xoff = (size_t)(b0 + b) * 1024 + u0 + u;

    float xpre[4];
    {
        const float* Xn = g_X + xoff;
#pragma unroll
        for (int g = 0; g < 4; g++) xpre[g] = __ldcs(Xn + g * 256);
    }

    for (int t = 0; t < 512; t++) {
        // fill h smem (bf16 hi/lo): 16 batches x 256 units, 1 uint4 per array
        if (t > 0) {
            const uint4* srcH = (const uint4*)(g_hH[(t + 1) & 1]);
            const uint4* srcL = (const uint4*)(g_hL[(t + 1) & 1]);
            int row = tid >> 5, c8 = tid & 31;
            uint4 vh = __ldcg(srcH + (size_t)(b0 + row) * 32 + c8);
            uint4 vl = __ldcg(srcL + (size_t)(b0 + row) * 32 + c8);
            *(uint4*)(shm + row * 528 + c8 * 16) = vh;
            *(uint4*)(shm + 8448 + row * 528 + c8 * 16) = vl;
        }
        // prefetch X(t+1)
        float xnext[4];
        if (t < 511) {
            const float* Xn = g_X + ((size_t)(t + 1) << 18) + xoff;
#pragma unroll
            for (int g = 0; g < 4; g++) xnext[g] = __ldcs(Xn + g * 256);
        }

        if (t > 0) {
            __syncthreads();
            float d[4][4];
#pragma unroll
            for (int j = 0; j < 4; j++)
#pragma unroll
                for (int q = 0; q < 4; q++) d[j][q] = 0.f;

#pragma unroll
            for (int kb = 0; kb < 4; kb++) {
                uint32_t aH[4], aL[4];
                uint32_t ar = sb + (uint32_t)((lane & 15) * 528
                                              + kg * 128 + kb * 32 + ((lane >> 4) << 4));
                ldsm_x4(aH[0], aH[1], aH[2], aH[3], ar);
                ldsm_x4(aL[0], aL[1], aL[2], aL[3], ar + 8448u);
#pragma unroll
                for (int j = 0; j < 4; j++) {
                    mma16816(d[j], aH, wH[j >> 1][kb][j & 1], wH[j >> 1][kb][2 + (j & 1)]);
                    mma16816(d[j], aL, wH[j >> 1][kb][j & 1], wH[j >> 1][kb][2 + (j & 1)]);
                    mma16816(d[j], aH, wL[j >> 1][kb][j & 1], wL[j >> 1][kb][2 + (j & 1)]);
                }
            }
            // scatter partials (rotate-by-8 col swizzle, 128 cols)
#pragma unroll
            for (int j = 0; j < 4; j++) {
                int bl = lane >> 2;
                int n = nt * 32 + j * 8 + (lane & 3) * 2;
                int c0 = (n + 8 * bl) & 127;
                *(float2*)(PS + kg * 2048 + bl * 128 + c0) = make_float2(d[j][0], d[j][1]);
                int bl2 = bl + 8;
                int c2 = (n + 8 * bl2) & 127;
                *(float2*)(PS + kg * 2048 + bl2 * 128 + c2) = make_float2(d[j][2], d[j][3]);
            }
            __syncthreads();
        }

        // reduce + gates
        float S[4];
#pragma unroll
        for (int g = 0; g < 4; g++) S[g] = xpre[g];
        if (t > 0) {
#pragma unroll
            for (int g = 0; g < 4; g++) {
                int cc = (g * 32 + u + 8 * b) & 127;
#pragma unroll
                for (int k2 = 0; k2 < 4; k2++)
                    S[g] += PS[k2 * 2048 + b * 128 + cc];
            }
        }
        float pf = sigm_fast(S[0]);
        float pi = sigm_fast(S[1]);
        float pu = sigm_fast(S[2]);
        float po = sigm_fast(S[3]);
        c = pf * c + pi * pu;
        float h = po * tanh_fast(c);

        __nv_bfloat16 hh = __float2bfloat16(h);
        __nv_bfloat16 hl = __float2bfloat16(h - __bfloat162float(hh));
        size_t hidx = (size_t)(b0 + b) * 256 + u0 + u;
        g_hH[t & 1][hidx] = hh;
        g_hL[t & 1][hidx] = hl;

#pragma unroll
        for (int g = 0; g < 4; g++) xpre[g] = xnext[g];

        if (t < 511) {
            __syncthreads();                      // all h stores issued CTA-wide
            if (tid == 0)
                st_release(&g_flags[myflag * 32], gen0 + (unsigned)t + 1u);
            out[(size_t)t * 65536 + (b0 + b) * 256 + u0 + u] = h;  // overlaps barrier
            if (tid < 8) {
                const unsigned* fp = &g_flags[(by * 8 + tid) * 32];
                unsigned want = gen0 + (unsigned)t + 1u;
                while ((int)(ld_acquire(fp) - want) < 0) { }
            }
            __syncthreads();
        } else {
            int gb = b0 + b;
            out[(size_t)t * 65536 + gb * 256 + u0 + u] = h;
            if (out_elems >= 33685504) {
                out[33554432 + gb * 256 + u0 + u] = h;   // hx
                out[33619968 + gb * 256 + u0 + u] = c;   // cx
            }
        }
    }
}

// ---------------------------------------------------------------------------
extern "C" void kernel_launch(void* const* d_in, const int* in_sizes, int n_in,
                              void* d_out, int out_size) {
    const float* x = (const float*)d_in[0];
    P12 p;
    if (n_in >= 13 && in_sizes[3] == 196608) {
        for (int g = 0; g < 4; g++) {
            p.W[g] = (const float*)d_in[1 + 2 * g];
            p.B[g] = (const float*)d_in[2 + 2 * g];
            p.R[g] = (const float*)d_in[9 + g];
        }
    } else {
        for (int g = 0; g < 4; g++) {
            p.W[g] = (const float*)d_in[1 + 3 * g];
            p.B[g] = (const float*)d_in[2 + 3 * g];
            p.R[g] = (const float*)d_in[3 + 3 * g];
        }
    }

    cvtA_kernel<<<4096, 256>>>(x);
    cvtW_kernel<<<2048, 256>>>(p);

    cudaFuncSetAttribute(g1mma_kernel, cudaFuncAttributeMaxDynamicSharedMemorySize, 196608);
    g1mma_kernel<<<dim3(4, 1024), 256, 196608>>>(p);

    cudaFuncSetAttribute(rnn_mma_kernel, cudaFuncAttributeMaxDynamicSharedMemorySize, 67584);
    rnn_mma_kernel<<<dim3(8, 16), 512, 67584>>>(p, (float*)d_out, out_size);
}